// round 1
// baseline (speedup 1.0000x reference)
#include <cuda_runtime.h>
#include <math.h>

// ---------------------------------------------------------------------------
// VSS stage: 2 VSS blocks. B=4, C=256, H=W=32 (L=1024), D_inner=512,
// dt_rank=16, d_state=16, K=4 directions.
// ---------------------------------------------------------------------------

#define BB   4
#define HH   32
#define WW   32
#define LL   1024            // H*W
#define CC   256             // DIM
#define DI   512             // D_INNER
#define RR   16              // DT_RANK
#define NS   16              // D_STATE
#define KK   4
#define NLAYER 2

// ------------------------- scratch (static device) -------------------------
__device__ float g_xnhwc  [BB * LL * CC];        // residual stream, NHWC
__device__ float g_xn     [BB * LL * CC];        // ln1 output
__device__ float g_xz     [BB * LL * 2 * DI];    // in_proj output (xc | z)
__device__ float g_urow   [BB * LL * DI];        // conv+silu, row order, (b,l,d)
__device__ float g_ucol   [BB * LL * DI];        // conv+silu, col order, (b,l',d)
__device__ float g_dts    [BB * KK * RR * LL];   // (bk, r, l)
__device__ float g_BC     [BB * KK * LL * 2*NS]; // (bk, l, 32)  [B | C]
__device__ float g_delta  [BB * KK * LL * DI];   // (bk, l, d)
__device__ float g_contrib[BB * KK * LL * DI];   // (bk, pos, d)
__device__ float g_yg     [BB * LL * DI];        // gated, pre-out_proj

// ------------------------- utilities ---------------------------------------
__device__ __forceinline__ float block_reduce_sum_256(float v, float* red, int tid) {
    #pragma unroll
    for (int o = 16; o > 0; o >>= 1) v += __shfl_xor_sync(0xffffffffu, v, o);
    int warp = tid >> 5, lane = tid & 31;
    if (lane == 0) red[warp] = v;
    __syncthreads();
    if (tid == 0) {
        float s = 0.f;
        #pragma unroll
        for (int w = 0; w < 8; w++) s += red[w];
        red[0] = s;
    }
    __syncthreads();
    float r = red[0];
    __syncthreads();
    return r;
}

// ------------------------- transpose (batched, 32x32 tiles) -----------------
// dst[b][c][r] = src[b][r][c];  rows, cols multiples of 32
__global__ void transpose_k(float* __restrict__ dst, const float* __restrict__ src,
                            int rows, int cols) {
    __shared__ float tile[32][33];
    int b  = blockIdx.z;
    int c0 = blockIdx.x * 32;
    int r0 = blockIdx.y * 32;
    const float* s = src + (size_t)b * rows * cols;
    float*       d = dst + (size_t)b * rows * cols;
    int tx = threadIdx.x, ty = threadIdx.y;
    #pragma unroll
    for (int i = 0; i < 32; i += 8)
        tile[ty + i][tx] = s[(size_t)(r0 + ty + i) * cols + c0 + tx];
    __syncthreads();
    #pragma unroll
    for (int i = 0; i < 32; i += 8)
        d[(size_t)(c0 + ty + i) * rows + r0 + tx] = tile[tx][ty + i];
}

// ------------------------- ln1 ---------------------------------------------
__global__ void ln1_kernel(const float* __restrict__ x, const float* __restrict__ w,
                           const float* __restrict__ bia, float* __restrict__ out) {
    __shared__ float red[32];
    int row = blockIdx.x;           // b*L + l   (4096 rows)
    int tid = threadIdx.x;          // 256
    float v = x[(size_t)row * CC + tid];
    float mean = block_reduce_sum_256(v, red, tid) * (1.f / CC);
    float xc = v - mean;
    float var = block_reduce_sum_256(xc * xc, red, tid) * (1.f / CC);
    out[(size_t)row * CC + tid] = xc * rsqrtf(var + 1e-6f) * w[tid] + bia[tid];
}

// ------------------------- generic NT GEMM (64x64 tile) ---------------------
// C[m,n] (+)= sum_k A[m,k] * B[n,k];  M,N mult of 64, K mult of 16
template <int EPI_ADD>
__global__ void gemm_nt64(const float* __restrict__ A, const float* __restrict__ Bm,
                          float* __restrict__ C, int M, int N, int Kd) {
    __shared__ __align__(16) float As[16][68];
    __shared__ __align__(16) float Bs[16][68];
    int m0 = blockIdx.y * 64, n0 = blockIdx.x * 64;
    int tid = threadIdx.x;              // 256
    int tx = tid & 15, ty = tid >> 4;
    float acc[4][4];
    #pragma unroll
    for (int i = 0; i < 4; i++)
        #pragma unroll
        for (int j = 0; j < 4; j++) acc[i][j] = 0.f;

    for (int k0 = 0; k0 < Kd; k0 += 16) {
        #pragma unroll
        for (int it = 0; it < 4; it++) {
            int e = tid + it * 256;
            int r = e >> 4, c = e & 15;
            As[c][r] = A[(size_t)(m0 + r) * Kd + k0 + c];
            Bs[c][r] = Bm[(size_t)(n0 + r) * Kd + k0 + c];
        }
        __syncthreads();
        #pragma unroll
        for (int kk = 0; kk < 16; kk++) {
            float4 a  = *(const float4*)&As[kk][ty * 4];
            float4 bv = *(const float4*)&Bs[kk][tx * 4];
            acc[0][0] += a.x * bv.x; acc[0][1] += a.x * bv.y; acc[0][2] += a.x * bv.z; acc[0][3] += a.x * bv.w;
            acc[1][0] += a.y * bv.x; acc[1][1] += a.y * bv.y; acc[1][2] += a.y * bv.z; acc[1][3] += a.y * bv.w;
            acc[2][0] += a.z * bv.x; acc[2][1] += a.z * bv.y; acc[2][2] += a.z * bv.z; acc[2][3] += a.z * bv.w;
            acc[3][0] += a.w * bv.x; acc[3][1] += a.w * bv.y; acc[3][2] += a.w * bv.z; acc[3][3] += a.w * bv.w;
        }
        __syncthreads();
    }
    #pragma unroll
    for (int i = 0; i < 4; i++) {
        int m = m0 + ty * 4 + i;
        float4* cp = (float4*)&C[(size_t)m * N + n0 + tx * 4];
        float4 v;
        if (EPI_ADD) {
            float4 old = *cp;
            v.x = old.x + acc[i][0]; v.y = old.y + acc[i][1];
            v.z = old.z + acc[i][2]; v.w = old.w + acc[i][3];
        } else {
            v.x = acc[i][0]; v.y = acc[i][1]; v.z = acc[i][2]; v.w = acc[i][3];
        }
        *cp = v;
    }
}

// ------------------------- depthwise conv 3x3 + bias + silu ------------------
// reads xc part of xz (NHWC), writes row-order and col-order copies, (b,l,d)
__global__ void conv_silu_kernel(const float* __restrict__ xz,
                                 const float* __restrict__ cw,   // (512,9)
                                 const float* __restrict__ cb,   // (512)
                                 float* __restrict__ urow, float* __restrict__ ucol) {
    int bid = blockIdx.x;               // B*L*2 = 8192 blocks
    int tid = threadIdx.x;              // 256
    int d  = ((bid & 1) << 8) + tid;
    int hw = (bid >> 1) & (LL - 1);
    int b  = bid >> 11;
    int h = hw >> 5, w = hw & 31;
    float acc = cb[d];
    const float* wt = cw + d * 9;
    const float* xb = xz + (size_t)b * LL * (2 * DI);
    #pragma unroll
    for (int i = 0; i < 3; i++) {
        int hh = h + i - 1;
        if ((unsigned)hh < (unsigned)HH) {
            #pragma unroll
            for (int jj = 0; jj < 3; jj++) {
                int ww = w + jj - 1;
                if ((unsigned)ww < (unsigned)WW)
                    acc += wt[i * 3 + jj] * xb[(size_t)(hh * WW + ww) * (2 * DI) + d];
            }
        }
    }
    float s = acc / (1.f + expf(-acc));
    urow[((size_t)b * LL + hw) * DI + d] = s;
    int posc = (w << 5) | h;            // column-major scan index
    ucol[((size_t)b * LL + posc) * DI + d] = s;
}

// ------------------------- x_proj GEMM: (48 x L) = W(48x512) @ U^T -----------
__global__ void gemm_xdbl(const float* __restrict__ xpw,   // (K,48,512) layer slice
                          const float* __restrict__ urow, const float* __restrict__ ucol,
                          float* __restrict__ dts, float* __restrict__ BC) {
    __shared__ float As[16][53];                    // [kk][c]
    __shared__ __align__(16) float Bs[16][68];      // [kk][l]
    int bk = blockIdx.y;                 // 16
    int b = bk >> 2, k = bk & 3;
    int l0 = blockIdx.x * 64;
    const float* A = xpw + (size_t)k * 48 * DI;
    const float* U = ((k & 1) ? ucol : urow) + (size_t)b * LL * DI;
    int tid = threadIdx.x;               // 256
    int tx = tid & 15, ty = tid >> 4;
    float acc[3][4];
    #pragma unroll
    for (int i = 0; i < 3; i++)
        #pragma unroll
        for (int j = 0; j < 4; j++) acc[i][j] = 0.f;

    for (int k0 = 0; k0 < DI; k0 += 16) {
        #pragma unroll
        for (int it = 0; it < 3; it++) {
            int e = tid + it * 256;      // 768 total
            int c = e >> 4, kk = e & 15;
            As[kk][c] = A[(size_t)c * DI + k0 + kk];
        }
        #pragma unroll
        for (int it = 0; it < 4; it++) {
            int e = tid + it * 256;      // 1024 total
            int l = e >> 4, kk = e & 15;
            Bs[kk][l] = U[(size_t)(l0 + l) * DI + k0 + kk];
        }
        __syncthreads();
        #pragma unroll
        for (int kk = 0; kk < 16; kk++) {
            float a0 = As[kk][ty * 3 + 0];
            float a1 = As[kk][ty * 3 + 1];
            float a2 = As[kk][ty * 3 + 2];
            float4 bv = *(const float4*)&Bs[kk][tx * 4];
            acc[0][0] += a0 * bv.x; acc[0][1] += a0 * bv.y; acc[0][2] += a0 * bv.z; acc[0][3] += a0 * bv.w;
            acc[1][0] += a1 * bv.x; acc[1][1] += a1 * bv.y; acc[1][2] += a1 * bv.z; acc[1][3] += a1 * bv.w;
            acc[2][0] += a2 * bv.x; acc[2][1] += a2 * bv.y; acc[2][2] += a2 * bv.z; acc[2][3] += a2 * bv.w;
        }
        __syncthreads();
    }
    #pragma unroll
    for (int i = 0; i < 3; i++) {
        int c = ty * 3 + i;
        #pragma unroll
        for (int j = 0; j < 4; j++) {
            int l = l0 + tx * 4 + j;
            float v = acc[i][j];
            if (c < RR) dts[((size_t)bk * RR + c) * LL + l] = v;
            else        BC[((size_t)bk * LL + l) * (2 * NS) + (c - RR)] = v;
        }
    }
}

// ------------------------- dt_proj + softplus --------------------------------
__global__ void delta_kernel(const float* __restrict__ dts,   // (bk, r, l)
                             const float* __restrict__ dtw,   // (K,512,16) layer
                             const float* __restrict__ dtb,   // (K,512)    layer
                             float* __restrict__ delta) {     // (bk, l, d)
    int d  = blockIdx.x * 256 + threadIdx.x;
    int l  = blockIdx.y;
    int bk = blockIdx.z;
    int k  = bk & 3;
    const float4* w4 = (const float4*)(dtw + (size_t)(k * DI + d) * RR);
    float4 w0 = w4[0], w1 = w4[1], w2 = w4[2], w3 = w4[3];
    const float* s = dts + (size_t)bk * RR * LL + l;
    float acc = dtb[k * DI + d];
    acc += w0.x * s[0*LL]  + w0.y * s[1*LL]  + w0.z * s[2*LL]  + w0.w * s[3*LL];
    acc += w1.x * s[4*LL]  + w1.y * s[5*LL]  + w1.z * s[6*LL]  + w1.w * s[7*LL];
    acc += w2.x * s[8*LL]  + w2.y * s[9*LL]  + w2.z * s[10*LL] + w2.w * s[11*LL];
    acc += w3.x * s[12*LL] + w3.y * s[13*LL] + w3.z * s[14*LL] + w3.w * s[15*LL];
    float sp = (acc > 20.f) ? acc : log1pf(expf(acc));
    delta[((size_t)bk * LL + l) * DI + d] = sp;
}

// ------------------------- selective scan ------------------------------------
// one thread per (b,k,d) channel, 16 states in registers, serial over L
__global__ __launch_bounds__(128) void scan_kernel(
        const float* __restrict__ delta,  // (bk,l,d)
        const float* __restrict__ urow,   // (b,l,d)
        const float* __restrict__ ucol,
        const float* __restrict__ BC,     // (bk,l,32)
        const float* __restrict__ A_log,  // (K*DI, 16) layer slice
        const float* __restrict__ Ds,     // (K*DI)     layer slice
        float* __restrict__ contrib) {    // (bk,pos,d)
    int cid = blockIdx.x * blockDim.x + threadIdx.x;   // 0..8191
    int d = cid & (DI - 1);
    int k = (cid >> 9) & 3;
    int b = cid >> 11;
    int bk = b * KK + k;

    float Aexp[NS];
    const float* arow = A_log + (size_t)(k * DI + d) * NS;
    #pragma unroll
    for (int n = 0; n < NS; n++) Aexp[n] = -expf(arow[n]);
    float Dv = Ds[k * DI + d];

    const float* u_base  = ((k & 1) ? ucol : urow) + (size_t)b * LL * DI + d;
    const float* dl_base = delta + (size_t)bk * LL * DI + d;
    const float4* bc_base = (const float4*)(BC + (size_t)bk * LL * (2 * NS));
    float* out_base = contrib + (size_t)bk * LL * DI + d;
    const bool rev = (k >= 2);

    float h[NS];
    #pragma unroll
    for (int n = 0; n < NS; n++) h[n] = 0.f;

    for (int t = 0; t < LL; t++) {
        int j = rev ? (LL - 1 - t) : t;
        float dv = dl_base[(size_t)j * DI];
        float u  = u_base[(size_t)j * DI];
        const float4* bc = bc_base + (size_t)j * 8;
        float du = dv * u;
        float y  = Dv * u;
        #pragma unroll
        for (int q = 0; q < 4; q++) {
            float4 Bq = bc[q];
            float4 Cq = bc[q + 4];
            float dA;
            dA = __expf(dv * Aexp[q*4+0]); h[q*4+0] = dA*h[q*4+0] + du*Bq.x; y += h[q*4+0]*Cq.x;
            dA = __expf(dv * Aexp[q*4+1]); h[q*4+1] = dA*h[q*4+1] + du*Bq.y; y += h[q*4+1]*Cq.y;
            dA = __expf(dv * Aexp[q*4+2]); h[q*4+2] = dA*h[q*4+2] + du*Bq.z; y += h[q*4+2]*Cq.z;
            dA = __expf(dv * Aexp[q*4+3]); h[q*4+3] = dA*h[q*4+3] + du*Bq.w; y += h[q*4+3]*Cq.w;
        }
        int pos = (k & 1) ? (((j & 31) << 5) | (j >> 5)) : j;
        out_base[(size_t)pos * DI] = y;
    }
}

// ------------------------- merge + out_norm + gate ---------------------------
__global__ void merge_ln_gate(const float* __restrict__ contrib,
                              const float* __restrict__ xz,
                              const float* __restrict__ onw,
                              const float* __restrict__ onb,
                              float* __restrict__ yg) {
    __shared__ float red[32];
    int row = blockIdx.x;         // b*L + l
    int b = row >> 10;
    int l = row & (LL - 1);
    int tid = threadIdx.x;        // 256
    float v[2];
    #pragma unroll
    for (int hh = 0; hh < 2; hh++) {
        int d = tid + hh * 256;
        size_t base = ((size_t)(b * KK) * LL + l) * DI + d;
        const size_t stride = (size_t)LL * DI;
        v[hh] = contrib[base] + contrib[base + stride]
              + contrib[base + 2 * stride] + contrib[base + 3 * stride];
    }
    float sum = block_reduce_sum_256(v[0] + v[1], red, tid);
    float mean = sum * (1.f / DI);
    float d0 = v[0] - mean, d1 = v[1] - mean;
    float sq = block_reduce_sum_256(d0 * d0 + d1 * d1, red, tid);
    float rstd = rsqrtf(sq * (1.f / DI) + 1e-5f);
    #pragma unroll
    for (int hh = 0; hh < 2; hh++) {
        int d = tid + hh * 256;
        float yn = (v[hh] - mean) * rstd * onw[d] + onb[d];
        float z = xz[(size_t)row * (2 * DI) + DI + d];
        yg[(size_t)row * DI + d] = yn * (z / (1.f + expf(-z)));
    }
}

// ---------------------------------------------------------------------------
extern "C" void kernel_launch(void* const* d_in, const int* in_sizes, int n_in,
                              void* d_out, int out_size) {
    const float* x          = (const float*)d_in[0];
    const float* ln1_w      = (const float*)d_in[1];
    const float* ln1_b      = (const float*)d_in[2];
    const float* in_proj_w  = (const float*)d_in[3];
    const float* conv_w     = (const float*)d_in[4];
    const float* conv_b     = (const float*)d_in[5];
    const float* x_proj_w   = (const float*)d_in[6];
    const float* dt_proj_w  = (const float*)d_in[7];
    const float* dt_proj_b  = (const float*)d_in[8];
    const float* A_log      = (const float*)d_in[9];
    const float* Ds         = (const float*)d_in[10];
    const float* out_norm_w = (const float*)d_in[11];
    const float* out_norm_b = (const float*)d_in[12];
    const float* out_proj_w = (const float*)d_in[13];

    float *xnhwc, *xn, *xz, *urow, *ucol, *dts, *bc, *delta, *contrib, *yg;
    cudaGetSymbolAddress((void**)&xnhwc,   g_xnhwc);
    cudaGetSymbolAddress((void**)&xn,      g_xn);
    cudaGetSymbolAddress((void**)&xz,      g_xz);
    cudaGetSymbolAddress((void**)&urow,    g_urow);
    cudaGetSymbolAddress((void**)&ucol,    g_ucol);
    cudaGetSymbolAddress((void**)&dts,     g_dts);
    cudaGetSymbolAddress((void**)&bc,      g_BC);
    cudaGetSymbolAddress((void**)&delta,   g_delta);
    cudaGetSymbolAddress((void**)&contrib, g_contrib);
    cudaGetSymbolAddress((void**)&yg,      g_yg);

    // NCHW -> NHWC
    transpose_k<<<dim3(LL / 32, CC / 32, BB), dim3(32, 8)>>>(xnhwc, x, CC, LL);

    for (int layer = 0; layer < NLAYER; layer++) {
        const float* l_ln1w = ln1_w      + (size_t)layer * CC;
        const float* l_ln1b = ln1_b      + (size_t)layer * CC;
        const float* l_ipw  = in_proj_w  + (size_t)layer * 2 * DI * CC;
        const float* l_cw   = conv_w     + (size_t)layer * DI * 9;
        const float* l_cb   = conv_b     + (size_t)layer * DI;
        const float* l_xpw  = x_proj_w   + (size_t)layer * KK * 48 * DI;
        const float* l_dtw  = dt_proj_w  + (size_t)layer * KK * DI * RR;
        const float* l_dtb  = dt_proj_b  + (size_t)layer * KK * DI;
        const float* l_alog = A_log      + (size_t)layer * KK * DI * NS;
        const float* l_ds   = Ds         + (size_t)layer * KK * DI;
        const float* l_onw  = out_norm_w + (size_t)layer * DI;
        const float* l_onb  = out_norm_b + (size_t)layer * DI;
        const float* l_opw  = out_proj_w + (size_t)layer * CC * DI;

        ln1_kernel<<<BB * LL, 256>>>(xnhwc, l_ln1w, l_ln1b, xn);
        gemm_nt64<0><<<dim3((2 * DI) / 64, (BB * LL) / 64), 256>>>(xn, l_ipw, xz,
                                                                    BB * LL, 2 * DI, CC);
        conv_silu_kernel<<<BB * LL * 2, 256>>>(xz, l_cw, l_cb, urow, ucol);
        gemm_xdbl<<<dim3(LL / 64, BB * KK), 256>>>(l_xpw, urow, ucol, dts, bc);
        delta_kernel<<<dim3(DI / 256, LL, BB * KK), 256>>>(dts, l_dtw, l_dtb, delta);
        scan_kernel<<<(BB * KK * DI) / 128, 128>>>(delta, urow, ucol, bc,
                                                   l_alog, l_ds, contrib);
        merge_ln_gate<<<BB * LL, 256>>>(contrib, xz, l_onw, l_onb, yg);
        gemm_nt64<1><<<dim3(CC / 64, (BB * LL) / 64), 256>>>(yg, l_opw, xnhwc,
                                                             BB * LL, CC, DI);
    }

    // NHWC -> NCHW
    transpose_k<<<dim3(CC / 32, LL / 32, BB), dim3(32, 8)>>>((float*)d_out, xnhwc, LL, CC);
}

// round 2
// speedup vs baseline: 3.0611x; 3.0611x over previous
#include <cuda_runtime.h>
#include <math.h>

// ---------------------------------------------------------------------------
// VSS stage: 2 VSS blocks. B=4, C=256, H=W=32 (L=1024), D_inner=512,
// dt_rank=16, d_state=16, K=4 directions.
// ---------------------------------------------------------------------------

#define BB   4
#define HH   32
#define WW   32
#define LL   1024            // H*W
#define CC   256             // DIM
#define DI   512             // D_INNER
#define RR   16              // DT_RANK
#define NS   16              // D_STATE
#define KK   4
#define NLAYER 2
#define NCH  16              // scan chunks
#define CH   64              // chunk length (NCH*CH == LL)

// ------------------------- scratch (static device) -------------------------
__device__ float g_xnhwc  [BB * LL * CC];        // residual stream, NHWC
__device__ float g_xn     [BB * LL * CC];        // ln1 output
__device__ float g_xz     [BB * LL * 2 * DI];    // in_proj output (xc | z)
__device__ float g_urow   [BB * LL * DI];        // conv+silu, row order, (b,l,d)
__device__ float g_ucol   [BB * LL * DI];        // conv+silu, col order, (b,l',d)
__device__ float g_dts    [BB * KK * RR * LL];   // (bk, r, l)
__device__ float g_BC     [BB * KK * LL * 2*NS]; // (bk, l, 32)  [B | C]
__device__ float g_hend   [BB * KK * NCH * DI * NS];  // chunk-local end states
__device__ float g_hstart [BB * KK * NCH * DI * NS];  // true chunk start states
__device__ float g_Ssum   [BB * KK * NCH * DI];       // per-chunk sum of delta
__device__ float g_contrib[BB * KK * LL * DI];   // (bk, pos, d)
__device__ float g_yg     [BB * LL * DI];        // gated, pre-out_proj

// ------------------------- utilities ---------------------------------------
__device__ __forceinline__ float block_reduce_sum_256(float v, float* red, int tid) {
    #pragma unroll
    for (int o = 16; o > 0; o >>= 1) v += __shfl_xor_sync(0xffffffffu, v, o);
    int warp = tid >> 5, lane = tid & 31;
    if (lane == 0) red[warp] = v;
    __syncthreads();
    if (tid == 0) {
        float s = 0.f;
        #pragma unroll
        for (int w = 0; w < 8; w++) s += red[w];
        red[0] = s;
    }
    __syncthreads();
    float r = red[0];
    __syncthreads();
    return r;
}

__device__ __forceinline__ float softplus_f(float x) {
    return (x > 20.f) ? x : log1pf(expf(x));
}

// ------------------------- transpose (batched, 32x32 tiles) -----------------
__global__ void transpose_k(float* __restrict__ dst, const float* __restrict__ src,
                            int rows, int cols) {
    __shared__ float tile[32][33];
    int b  = blockIdx.z;
    int c0 = blockIdx.x * 32;
    int r0 = blockIdx.y * 32;
    const float* s = src + (size_t)b * rows * cols;
    float*       d = dst + (size_t)b * rows * cols;
    int tx = threadIdx.x, ty = threadIdx.y;
    #pragma unroll
    for (int i = 0; i < 32; i += 8)
        tile[ty + i][tx] = s[(size_t)(r0 + ty + i) * cols + c0 + tx];
    __syncthreads();
    #pragma unroll
    for (int i = 0; i < 32; i += 8)
        d[(size_t)(c0 + ty + i) * rows + r0 + tx] = tile[tx][ty + i];
}

// ------------------------- ln1 ---------------------------------------------
__global__ void ln1_kernel(const float* __restrict__ x, const float* __restrict__ w,
                           const float* __restrict__ bia, float* __restrict__ out) {
    __shared__ float red[32];
    int row = blockIdx.x;
    int tid = threadIdx.x;
    float v = x[(size_t)row * CC + tid];
    float mean = block_reduce_sum_256(v, red, tid) * (1.f / CC);
    float xc = v - mean;
    float var = block_reduce_sum_256(xc * xc, red, tid) * (1.f / CC);
    out[(size_t)row * CC + tid] = xc * rsqrtf(var + 1e-6f) * w[tid] + bia[tid];
}

// ------------------------- generic NT GEMM (64x64 tile) ---------------------
template <int EPI_ADD>
__global__ void gemm_nt64(const float* __restrict__ A, const float* __restrict__ Bm,
                          float* __restrict__ C, int M, int N, int Kd) {
    __shared__ __align__(16) float As[16][68];
    __shared__ __align__(16) float Bs[16][68];
    int m0 = blockIdx.y * 64, n0 = blockIdx.x * 64;
    int tid = threadIdx.x;
    int tx = tid & 15, ty = tid >> 4;
    float acc[4][4];
    #pragma unroll
    for (int i = 0; i < 4; i++)
        #pragma unroll
        for (int j = 0; j < 4; j++) acc[i][j] = 0.f;

    for (int k0 = 0; k0 < Kd; k0 += 16) {
        #pragma unroll
        for (int it = 0; it < 4; it++) {
            int e = tid + it * 256;
            int r = e >> 4, c = e & 15;
            As[c][r] = A[(size_t)(m0 + r) * Kd + k0 + c];
            Bs[c][r] = Bm[(size_t)(n0 + r) * Kd + k0 + c];
        }
        __syncthreads();
        #pragma unroll
        for (int kk = 0; kk < 16; kk++) {
            float4 a  = *(const float4*)&As[kk][ty * 4];
            float4 bv = *(const float4*)&Bs[kk][tx * 4];
            acc[0][0] += a.x * bv.x; acc[0][1] += a.x * bv.y; acc[0][2] += a.x * bv.z; acc[0][3] += a.x * bv.w;
            acc[1][0] += a.y * bv.x; acc[1][1] += a.y * bv.y; acc[1][2] += a.y * bv.z; acc[1][3] += a.y * bv.w;
            acc[2][0] += a.z * bv.x; acc[2][1] += a.z * bv.y; acc[2][2] += a.z * bv.z; acc[2][3] += a.z * bv.w;
            acc[3][0] += a.w * bv.x; acc[3][1] += a.w * bv.y; acc[3][2] += a.w * bv.z; acc[3][3] += a.w * bv.w;
        }
        __syncthreads();
    }
    #pragma unroll
    for (int i = 0; i < 4; i++) {
        int m = m0 + ty * 4 + i;
        float4* cp = (float4*)&C[(size_t)m * N + n0 + tx * 4];
        float4 v;
        if (EPI_ADD) {
            float4 old = *cp;
            v.x = old.x + acc[i][0]; v.y = old.y + acc[i][1];
            v.z = old.z + acc[i][2]; v.w = old.w + acc[i][3];
        } else {
            v.x = acc[i][0]; v.y = acc[i][1]; v.z = acc[i][2]; v.w = acc[i][3];
        }
        *cp = v;
    }
}

// ------------------------- depthwise conv 3x3 + bias + silu ------------------
__global__ void conv_silu_kernel(const float* __restrict__ xz,
                                 const float* __restrict__ cw,
                                 const float* __restrict__ cb,
                                 float* __restrict__ urow, float* __restrict__ ucol) {
    int bid = blockIdx.x;               // B*L*2 = 8192 blocks
    int tid = threadIdx.x;              // 256
    int d  = ((bid & 1) << 8) + tid;
    int hw = (bid >> 1) & (LL - 1);
    int b  = bid >> 11;
    int h = hw >> 5, w = hw & 31;
    float acc = cb[d];
    const float* wt = cw + d * 9;
    const float* xb = xz + (size_t)b * LL * (2 * DI);
    #pragma unroll
    for (int i = 0; i < 3; i++) {
        int hh = h + i - 1;
        if ((unsigned)hh < (unsigned)HH) {
            #pragma unroll
            for (int jj = 0; jj < 3; jj++) {
                int ww = w + jj - 1;
                if ((unsigned)ww < (unsigned)WW)
                    acc += wt[i * 3 + jj] * xb[(size_t)(hh * WW + ww) * (2 * DI) + d];
            }
        }
    }
    float s = acc / (1.f + expf(-acc));
    urow[((size_t)b * LL + hw) * DI + d] = s;
    int posc = (w << 5) | h;
    ucol[((size_t)b * LL + posc) * DI + d] = s;
}

// ------------------------- x_proj GEMM: (48 x L) = W(48x512) @ U^T -----------
__global__ void gemm_xdbl(const float* __restrict__ xpw,
                          const float* __restrict__ urow, const float* __restrict__ ucol,
                          float* __restrict__ dts, float* __restrict__ BC) {
    __shared__ float As[16][53];
    __shared__ __align__(16) float Bs[16][68];
    int bk = blockIdx.y;
    int b = bk >> 2, k = bk & 3;
    int l0 = blockIdx.x * 64;
    const float* A = xpw + (size_t)k * 48 * DI;
    const float* U = ((k & 1) ? ucol : urow) + (size_t)b * LL * DI;
    int tid = threadIdx.x;
    int tx = tid & 15, ty = tid >> 4;
    float acc[3][4];
    #pragma unroll
    for (int i = 0; i < 3; i++)
        #pragma unroll
        for (int j = 0; j < 4; j++) acc[i][j] = 0.f;

    for (int k0 = 0; k0 < DI; k0 += 16) {
        #pragma unroll
        for (int it = 0; it < 3; it++) {
            int e = tid + it * 256;
            int c = e >> 4, kk = e & 15;
            As[kk][c] = A[(size_t)c * DI + k0 + kk];
        }
        #pragma unroll
        for (int it = 0; it < 4; it++) {
            int e = tid + it * 256;
            int l = e >> 4, kk = e & 15;
            Bs[kk][l] = U[(size_t)(l0 + l) * DI + k0 + kk];
        }
        __syncthreads();
        #pragma unroll
        for (int kk = 0; kk < 16; kk++) {
            float a0 = As[kk][ty * 3 + 0];
            float a1 = As[kk][ty * 3 + 1];
            float a2 = As[kk][ty * 3 + 2];
            float4 bv = *(const float4*)&Bs[kk][tx * 4];
            acc[0][0] += a0 * bv.x; acc[0][1] += a0 * bv.y; acc[0][2] += a0 * bv.z; acc[0][3] += a0 * bv.w;
            acc[1][0] += a1 * bv.x; acc[1][1] += a1 * bv.y; acc[1][2] += a1 * bv.z; acc[1][3] += a1 * bv.w;
            acc[2][0] += a2 * bv.x; acc[2][1] += a2 * bv.y; acc[2][2] += a2 * bv.z; acc[2][3] += a2 * bv.w;
        }
        __syncthreads();
    }
    #pragma unroll
    for (int i = 0; i < 3; i++) {
        int c = ty * 3 + i;
        #pragma unroll
        for (int j = 0; j < 4; j++) {
            int l = l0 + tx * 4 + j;
            float v = acc[i][j];
            if (c < RR) dts[((size_t)bk * RR + c) * LL + l] = v;
            else        BC[((size_t)bk * LL + l) * (2 * NS) + (c - RR)] = v;
        }
    }
}

// ------------------------- chunked selective scan ----------------------------
// PASS2=0: compute per-chunk local end-state (h0=0) + sum of delta.
// PASS2=1: re-run each chunk from the true start state, emit y into contrib.
// dt_proj + softplus fused (weights in regs, dts tile in smem).
template <int PASS2>
__global__ __launch_bounds__(128) void scan_chunk_kernel(
        const float* __restrict__ urow, const float* __restrict__ ucol,
        const float* __restrict__ BC,
        const float* __restrict__ dts,    // (bk, r, l)
        const float* __restrict__ dtw,    // (K,512,16) layer slice
        const float* __restrict__ dtb,    // (K,512)    layer slice
        const float* __restrict__ A_log,  // (K*DI, 16) layer slice
        const float* __restrict__ Ds,     // (K*DI)     layer slice
        const float* __restrict__ hstart, // pass2 in
        float* __restrict__ hend,         // pass1 out
        float* __restrict__ Ssum,         // pass1 out
        float* __restrict__ contrib) {    // pass2 out
    __shared__ float s_dts[RR][CH];
    int tid = threadIdx.x;
    int d  = blockIdx.x * 128 + tid;
    int c  = blockIdx.y;
    int bk = blockIdx.z;
    int k = bk & 3, b = bk >> 2;
    const bool rev = (k >= 2);
    int jbase = rev ? (LL - CH * (c + 1)) : CH * c;

    // stage the dts tile for this chunk
    #pragma unroll
    for (int idx = tid; idx < RR * CH; idx += 128) {
        int r = idx >> 6, i = idx & (CH - 1);
        s_dts[r][i] = dts[((size_t)bk * RR + r) * LL + jbase + i];
    }
    __syncthreads();

    // dt_proj weights + bias
    float w[RR];
    const float4* w4 = (const float4*)(dtw + (size_t)(k * DI + d) * RR);
    #pragma unroll
    for (int q = 0; q < 4; q++) {
        float4 t = w4[q];
        w[q*4+0] = t.x; w[q*4+1] = t.y; w[q*4+2] = t.z; w[q*4+3] = t.w;
    }
    float bias = dtb[k * DI + d];

    // A row; detect A[n] == (n+1)*A[0] structure (true for this model)
    const float* arow = A_log + (size_t)(k * DI + d) * NS;
    float a0 = -expf(arow[0]);
    bool trick = true;
    #pragma unroll
    for (int n = 1; n < NS; n++) {
        float an = -expf(arow[n]);
        if (fabsf(an - (float)(n + 1) * a0) > 1e-5f * fabsf(an)) trick = false;
    }

    float h[NS];
    size_t hbase = ((size_t)(bk * NCH + c) * DI + d) * NS;
    if (PASS2) {
        const float4* hp = (const float4*)(hstart + hbase);
        #pragma unroll
        for (int q = 0; q < 4; q++) {
            float4 t = hp[q];
            h[q*4+0] = t.x; h[q*4+1] = t.y; h[q*4+2] = t.z; h[q*4+3] = t.w;
        }
    } else {
        #pragma unroll
        for (int n = 0; n < NS; n++) h[n] = 0.f;
    }
    float Dv = PASS2 ? Ds[k * DI + d] : 0.f;

    const float* u_base  = ((k & 1) ? ucol : urow) + (size_t)b * LL * DI + d;
    const float4* bc_base = (const float4*)(BC + (size_t)bk * LL * (2 * NS));
    float* out_base = PASS2 ? (contrib + (size_t)bk * LL * DI + d) : (float*)0;
    float S = 0.f;

    if (trick) {
        for (int t = 0; t < CH; t++) {
            int jl = rev ? (CH - 1 - t) : t;
            int j  = jbase + jl;
            float acc = bias;
            #pragma unroll
            for (int r = 0; r < RR; r++) acc += w[r] * s_dts[r][jl];
            float dv = softplus_f(acc);
            S += dv;
            float u  = u_base[(size_t)j * DI];
            float du = dv * u;
            const float4* bc = bc_base + (size_t)j * 8;
            float x = __expf(dv * a0);
            float p = x;
            float y = Dv * u;
            #pragma unroll
            for (int q = 0; q < 4; q++) {
                float4 Bq = bc[q];
                float4 Cq;
                if (PASS2) Cq = bc[q + 4];
                h[q*4+0] = p*h[q*4+0] + du*Bq.x; if (PASS2) y += h[q*4+0]*Cq.x; p *= x;
                h[q*4+1] = p*h[q*4+1] + du*Bq.y; if (PASS2) y += h[q*4+1]*Cq.y; p *= x;
                h[q*4+2] = p*h[q*4+2] + du*Bq.z; if (PASS2) y += h[q*4+2]*Cq.z; p *= x;
                h[q*4+3] = p*h[q*4+3] + du*Bq.w; if (PASS2) y += h[q*4+3]*Cq.w;
                if (q < 3) p *= x;
            }
            if (PASS2) {
                int pos = (k & 1) ? (((j & 31) << 5) | (j >> 5)) : j;
                out_base[(size_t)pos * DI] = y;
            }
        }
    } else {
        float Aexp[NS];
        #pragma unroll
        for (int n = 0; n < NS; n++) Aexp[n] = -expf(arow[n]);
        for (int t = 0; t < CH; t++) {
            int jl = rev ? (CH - 1 - t) : t;
            int j  = jbase + jl;
            float acc = bias;
            #pragma unroll
            for (int r = 0; r < RR; r++) acc += w[r] * s_dts[r][jl];
            float dv = softplus_f(acc);
            S += dv;
            float u  = u_base[(size_t)j * DI];
            float du = dv * u;
            const float4* bc = bc_base + (size_t)j * 8;
            float y = Dv * u;
            #pragma unroll
            for (int q = 0; q < 4; q++) {
                float4 Bq = bc[q];
                float4 Cq;
                if (PASS2) Cq = bc[q + 4];
                float dA;
                dA = __expf(dv*Aexp[q*4+0]); h[q*4+0] = dA*h[q*4+0] + du*Bq.x; if (PASS2) y += h[q*4+0]*Cq.x;
                dA = __expf(dv*Aexp[q*4+1]); h[q*4+1] = dA*h[q*4+1] + du*Bq.y; if (PASS2) y += h[q*4+1]*Cq.y;
                dA = __expf(dv*Aexp[q*4+2]); h[q*4+2] = dA*h[q*4+2] + du*Bq.z; if (PASS2) y += h[q*4+2]*Cq.z;
                dA = __expf(dv*Aexp[q*4+3]); h[q*4+3] = dA*h[q*4+3] + du*Bq.w; if (PASS2) y += h[q*4+3]*Cq.w;
            }
            if (PASS2) {
                int pos = (k & 1) ? (((j & 31) << 5) | (j >> 5)) : j;
                out_base[(size_t)pos * DI] = y;
            }
        }
    }

    if (!PASS2) {
        float4* hp = (float4*)(hend + hbase);
        #pragma unroll
        for (int q = 0; q < 4; q++)
            hp[q] = make_float4(h[q*4+0], h[q*4+1], h[q*4+2], h[q*4+3]);
        Ssum[(size_t)(bk * NCH + c) * DI + d] = S;
    }
}

// combine chunk summaries sequentially -> true start state per chunk
__global__ __launch_bounds__(128) void scan_combine_kernel(
        const float* __restrict__ hend, const float* __restrict__ Ssum,
        const float* __restrict__ A_log, float* __restrict__ hstart) {
    int cid = blockIdx.x * 128 + threadIdx.x;   // 0..8191 = bk*512+d
    int d  = cid & (DI - 1);
    int bk = cid >> 9;
    int k  = bk & 3;

    const float* arow = A_log + (size_t)(k * DI + d) * NS;
    float a0 = -expf(arow[0]);
    bool trick = true;
    #pragma unroll
    for (int n = 1; n < NS; n++) {
        float an = -expf(arow[n]);
        if (fabsf(an - (float)(n + 1) * a0) > 1e-5f * fabsf(an)) trick = false;
    }

    float h[NS];
    #pragma unroll
    for (int n = 0; n < NS; n++) h[n] = 0.f;

    for (int c = 0; c < NCH; c++) {
        size_t base = ((size_t)(bk * NCH + c) * DI + d) * NS;
        float4* hs = (float4*)(hstart + base);
        #pragma unroll
        for (int q = 0; q < 4; q++)
            hs[q] = make_float4(h[q*4+0], h[q*4+1], h[q*4+2], h[q*4+3]);

        float S = Ssum[(size_t)(bk * NCH + c) * DI + d];
        const float4* hp = (const float4*)(hend + base);
        if (trick) {
            float x = __expf(S * a0);
            float p = x;
            #pragma unroll
            for (int q = 0; q < 4; q++) {
                float4 he = hp[q];
                h[q*4+0] = p*h[q*4+0] + he.x; p *= x;
                h[q*4+1] = p*h[q*4+1] + he.y; p *= x;
                h[q*4+2] = p*h[q*4+2] + he.z; p *= x;
                h[q*4+3] = p*h[q*4+3] + he.w;
                if (q < 3) p *= x;
            }
        } else {
            #pragma unroll
            for (int q = 0; q < 4; q++) {
                float4 he = hp[q];
                h[q*4+0] = __expf(S * -expf(arow[q*4+0]))*h[q*4+0] + he.x;
                h[q*4+1] = __expf(S * -expf(arow[q*4+1]))*h[q*4+1] + he.y;
                h[q*4+2] = __expf(S * -expf(arow[q*4+2]))*h[q*4+2] + he.z;
                h[q*4+3] = __expf(S * -expf(arow[q*4+3]))*h[q*4+3] + he.w;
            }
        }
    }
}

// ------------------------- merge + out_norm + gate ---------------------------
__global__ void merge_ln_gate(const float* __restrict__ contrib,
                              const float* __restrict__ xz,
                              const float* __restrict__ onw,
                              const float* __restrict__ onb,
                              float* __restrict__ yg) {
    __shared__ float red[32];
    int row = blockIdx.x;
    int b = row >> 10;
    int l = row & (LL - 1);
    int tid = threadIdx.x;
    float v[2];
    #pragma unroll
    for (int hh = 0; hh < 2; hh++) {
        int d = tid + hh * 256;
        size_t base = ((size_t)(b * KK) * LL + l) * DI + d;
        const size_t stride = (size_t)LL * DI;
        v[hh] = contrib[base] + contrib[base + stride]
              + contrib[base + 2 * stride] + contrib[base + 3 * stride];
    }
    float sum = block_reduce_sum_256(v[0] + v[1], red, tid);
    float mean = sum * (1.f / DI);
    float d0 = v[0] - mean, d1 = v[1] - mean;
    float sq = block_reduce_sum_256(d0 * d0 + d1 * d1, red, tid);
    float rstd = rsqrtf(sq * (1.f / DI) + 1e-5f);
    #pragma unroll
    for (int hh = 0; hh < 2; hh++) {
        int d = tid + hh * 256;
        float yn = (v[hh] - mean) * rstd * onw[d] + onb[d];
        float z = xz[(size_t)row * (2 * DI) + DI + d];
        yg[(size_t)row * DI + d] = yn * (z / (1.f + expf(-z)));
    }
}

// ---------------------------------------------------------------------------
extern "C" void kernel_launch(void* const* d_in, const int* in_sizes, int n_in,
                              void* d_out, int out_size) {
    const float* x          = (const float*)d_in[0];
    const float* ln1_w      = (const float*)d_in[1];
    const float* ln1_b      = (const float*)d_in[2];
    const float* in_proj_w  = (const float*)d_in[3];
    const float* conv_w     = (const float*)d_in[4];
    const float* conv_b     = (const float*)d_in[5];
    const float* x_proj_w   = (const float*)d_in[6];
    const float* dt_proj_w  = (const float*)d_in[7];
    const float* dt_proj_b  = (const float*)d_in[8];
    const float* A_log      = (const float*)d_in[9];
    const float* Ds         = (const float*)d_in[10];
    const float* out_norm_w = (const float*)d_in[11];
    const float* out_norm_b = (const float*)d_in[12];
    const float* out_proj_w = (const float*)d_in[13];

    float *xnhwc, *xn, *xz, *urow, *ucol, *dts, *bc, *hend, *hstart, *ssum, *contrib, *yg;
    cudaGetSymbolAddress((void**)&xnhwc,   g_xnhwc);
    cudaGetSymbolAddress((void**)&xn,      g_xn);
    cudaGetSymbolAddress((void**)&xz,      g_xz);
    cudaGetSymbolAddress((void**)&urow,    g_urow);
    cudaGetSymbolAddress((void**)&ucol,    g_ucol);
    cudaGetSymbolAddress((void**)&dts,     g_dts);
    cudaGetSymbolAddress((void**)&bc,      g_BC);
    cudaGetSymbolAddress((void**)&hend,    g_hend);
    cudaGetSymbolAddress((void**)&hstart,  g_hstart);
    cudaGetSymbolAddress((void**)&ssum,    g_Ssum);
    cudaGetSymbolAddress((void**)&contrib, g_contrib);
    cudaGetSymbolAddress((void**)&yg,      g_yg);

    // NCHW -> NHWC
    transpose_k<<<dim3(LL / 32, CC / 32, BB), dim3(32, 8)>>>(xnhwc, x, CC, LL);

    for (int layer = 0; layer < NLAYER; layer++) {
        const float* l_ln1w = ln1_w      + (size_t)layer * CC;
        const float* l_ln1b = ln1_b      + (size_t)layer * CC;
        const float* l_ipw  = in_proj_w  + (size_t)layer * 2 * DI * CC;
        const float* l_cw   = conv_w     + (size_t)layer * DI * 9;
        const float* l_cb   = conv_b     + (size_t)layer * DI;
        const float* l_xpw  = x_proj_w   + (size_t)layer * KK * 48 * DI;
        const float* l_dtw  = dt_proj_w  + (size_t)layer * KK * DI * RR;
        const float* l_dtb  = dt_proj_b  + (size_t)layer * KK * DI;
        const float* l_alog = A_log      + (size_t)layer * KK * DI * NS;
        const float* l_ds   = Ds         + (size_t)layer * KK * DI;
        const float* l_onw  = out_norm_w + (size_t)layer * DI;
        const float* l_onb  = out_norm_b + (size_t)layer * DI;
        const float* l_opw  = out_proj_w + (size_t)layer * CC * DI;

        ln1_kernel<<<BB * LL, 256>>>(xnhwc, l_ln1w, l_ln1b, xn);
        gemm_nt64<0><<<dim3((2 * DI) / 64, (BB * LL) / 64), 256>>>(xn, l_ipw, xz,
                                                                    BB * LL, 2 * DI, CC);
        conv_silu_kernel<<<BB * LL * 2, 256>>>(xz, l_cw, l_cb, urow, ucol);
        gemm_xdbl<<<dim3(LL / 64, BB * KK), 256>>>(l_xpw, urow, ucol, dts, bc);

        scan_chunk_kernel<0><<<dim3(DI / 128, NCH, BB * KK), 128>>>(
            urow, ucol, bc, dts, l_dtw, l_dtb, l_alog, l_ds,
            (const float*)0, hend, ssum, (float*)0);
        scan_combine_kernel<<<(BB * KK * DI) / 128, 128>>>(hend, ssum, l_alog, hstart);
        scan_chunk_kernel<1><<<dim3(DI / 128, NCH, BB * KK), 128>>>(
            urow, ucol, bc, dts, l_dtw, l_dtb, l_alog, l_ds,
            hstart, (float*)0, (float*)0, contrib);

        merge_ln_gate<<<BB * LL, 256>>>(contrib, xz, l_onw, l_onb, yg);
        gemm_nt64<1><<<dim3(CC / 64, (BB * LL) / 64), 256>>>(yg, l_opw, xnhwc,
                                                             BB * LL, CC, DI);
    }

    // NHWC -> NCHW
    transpose_k<<<dim3(CC / 32, LL / 32, BB), dim3(32, 8)>>>((float*)d_out, xnhwc, LL, CC);
}

// round 3
// speedup vs baseline: 3.0619x; 1.0003x over previous
#include <cuda_runtime.h>
#include <math.h>

// ---------------------------------------------------------------------------
// VSS stage: 2 VSS blocks. B=4, C=256, H=W=32 (L=1024), D_inner=512,
// dt_rank=16, d_state=16, K=4 directions.
// ---------------------------------------------------------------------------

#define BB   4
#define HH   32
#define WW   32
#define LL   1024            // H*W
#define CC   256             // DIM
#define DI   512             // D_INNER
#define RR   16              // DT_RANK
#define NS   16              // D_STATE
#define KK   4
#define NLAYER 2
#define NCH  16              // scan chunks
#define CH   64              // chunk length (NCH*CH == LL)

// ------------------------- scratch (static device) -------------------------
__device__ float g_xnhwc  [BB * LL * CC];        // residual stream, NHWC
__device__ float g_xn     [BB * LL * CC];        // ln1 output
__device__ float g_xz     [BB * LL * 2 * DI];    // in_proj output (xc | z)
__device__ float g_urow   [BB * LL * DI];        // conv+silu, row order, (b,l,d)
__device__ float g_ucol   [BB * LL * DI];        // conv+silu, col order, (b,l',d)
__device__ float g_dts    [BB * KK * RR * LL];   // (bk, r, l)
__device__ float g_BC     [BB * KK * LL * 2*NS]; // (bk, l, 32)  [B | C]
__device__ float g_hend   [BB * KK * NCH * DI * NS];  // chunk-local end states
__device__ float g_hstart [BB * KK * NCH * DI * NS];  // true chunk start states
__device__ float g_Ssum   [BB * KK * NCH * DI];       // per-chunk sum of delta
__device__ float g_contrib[BB * KK * LL * DI];   // (bk, pos, d)
__device__ float g_yg     [BB * LL * DI];        // gated, pre-out_proj

// ------------------------- utilities ---------------------------------------
__device__ __forceinline__ float block_reduce_sum_256(float v, float* red, int tid) {
    #pragma unroll
    for (int o = 16; o > 0; o >>= 1) v += __shfl_xor_sync(0xffffffffu, v, o);
    int warp = tid >> 5, lane = tid & 31;
    if (lane == 0) red[warp] = v;
    __syncthreads();
    if (tid == 0) {
        float s = 0.f;
        #pragma unroll
        for (int w = 0; w < 8; w++) s += red[w];
        red[0] = s;
    }
    __syncthreads();
    float r = red[0];
    __syncthreads();
    return r;
}

__device__ __forceinline__ float softplus_f(float x) {
    return (x > 20.f) ? x : log1pf(expf(x));
}

// ------------------------- transpose (batched, 32x32 tiles) -----------------
__global__ void transpose_k(float* __restrict__ dst, const float* __restrict__ src,
                            int rows, int cols) {
    __shared__ float tile[32][33];
    int b  = blockIdx.z;
    int c0 = blockIdx.x * 32;
    int r0 = blockIdx.y * 32;
    const float* s = src + (size_t)b * rows * cols;
    float*       d = dst + (size_t)b * rows * cols;
    int tx = threadIdx.x, ty = threadIdx.y;
    #pragma unroll
    for (int i = 0; i < 32; i += 8)
        tile[ty + i][tx] = s[(size_t)(r0 + ty + i) * cols + c0 + tx];
    __syncthreads();
    #pragma unroll
    for (int i = 0; i < 32; i += 8)
        d[(size_t)(c0 + ty + i) * rows + r0 + tx] = tile[tx][ty + i];
}

// ------------------------- ln1 ---------------------------------------------
__global__ void ln1_kernel(const float* __restrict__ x, const float* __restrict__ w,
                           const float* __restrict__ bia, float* __restrict__ out) {
    __shared__ float red[32];
    int row = blockIdx.x;
    int tid = threadIdx.x;
    float v = x[(size_t)row * CC + tid];
    float mean = block_reduce_sum_256(v, red, tid) * (1.f / CC);
    float xc = v - mean;
    float var = block_reduce_sum_256(xc * xc, red, tid) * (1.f / CC);
    out[(size_t)row * CC + tid] = xc * rsqrtf(var + 1e-6f) * w[tid] + bia[tid];
}

// ------------------------- big NT GEMM (128 x BN tile) ----------------------
// C[m,n] (+)= sum_k A[m,k] * B[n,k];  M mult of 128, N mult of BN, K mult of 16
// 256 threads; microtile (128/(256/(BN/8))) x 8.  FMA-bound (not LDS-bound).
template <int BN, int EPI_ADD>
__global__ __launch_bounds__(256, 2) void gemm_big(
        const float* __restrict__ A, const float* __restrict__ Bm,
        float* __restrict__ C, int M, int N, int Kd) {
    constexpr int NT  = BN / 8;            // threads along n (16 or 8)
    constexpr int MT  = 256 / NT;          // threads along m (16 or 32)
    constexpr int MM  = 128 / MT;          // rows per thread (8 or 4)
    constexpr int ITB = (BN * 16) / 1024;  // B-stage float4 iters (2 or 1)
    __shared__ __align__(16) float As[16][132];
    __shared__ __align__(16) float Bs[16][BN + 4];

    int m0 = blockIdx.y * 128, n0 = blockIdx.x * BN;
    int tid = threadIdx.x;
    int tx = tid % NT, ty = tid / NT;

    float acc[MM][8];
    #pragma unroll
    for (int i = 0; i < MM; i++)
        #pragma unroll
        for (int j = 0; j < 8; j++) acc[i][j] = 0.f;

    const float* Ab = A  + (size_t)m0 * Kd;
    const float* Bb = Bm + (size_t)n0 * Kd;

    float4 pa[2], pb[ITB];
    // prefetch stage 0
    #pragma unroll
    for (int it = 0; it < 2; it++) {
        int e = tid + it * 256;
        pa[it] = *(const float4*)&Ab[(size_t)(e >> 2) * Kd + (e & 3) * 4];
    }
    #pragma unroll
    for (int it = 0; it < ITB; it++) {
        int e = tid + it * 256;
        pb[it] = *(const float4*)&Bb[(size_t)(e >> 2) * Kd + (e & 3) * 4];
    }

    for (int k0 = 0; k0 < Kd; k0 += 16) {
        __syncthreads();
        #pragma unroll
        for (int it = 0; it < 2; it++) {
            int e = tid + it * 256;
            int r = e >> 2, c4 = (e & 3) * 4;
            As[c4 + 0][r] = pa[it].x; As[c4 + 1][r] = pa[it].y;
            As[c4 + 2][r] = pa[it].z; As[c4 + 3][r] = pa[it].w;
        }
        #pragma unroll
        for (int it = 0; it < ITB; it++) {
            int e = tid + it * 256;
            int r = e >> 2, c4 = (e & 3) * 4;
            Bs[c4 + 0][r] = pb[it].x; Bs[c4 + 1][r] = pb[it].y;
            Bs[c4 + 2][r] = pb[it].z; Bs[c4 + 3][r] = pb[it].w;
        }
        __syncthreads();
        if (k0 + 16 < Kd) {
            #pragma unroll
            for (int it = 0; it < 2; it++) {
                int e = tid + it * 256;
                pa[it] = *(const float4*)&Ab[(size_t)(e >> 2) * Kd + k0 + 16 + (e & 3) * 4];
            }
            #pragma unroll
            for (int it = 0; it < ITB; it++) {
                int e = tid + it * 256;
                pb[it] = *(const float4*)&Bb[(size_t)(e >> 2) * Kd + k0 + 16 + (e & 3) * 4];
            }
        }
        #pragma unroll
        for (int kk = 0; kk < 16; kk++) {
            float av[MM];
            #pragma unroll
            for (int i = 0; i < MM / 4; i++) {
                float4 t = *(const float4*)&As[kk][ty * MM + i * 4];
                av[i*4+0] = t.x; av[i*4+1] = t.y; av[i*4+2] = t.z; av[i*4+3] = t.w;
            }
            float4 b0 = *(const float4*)&Bs[kk][tx * 8];
            float4 b1 = *(const float4*)&Bs[kk][tx * 8 + 4];
            #pragma unroll
            for (int i = 0; i < MM; i++) {
                acc[i][0] += av[i] * b0.x; acc[i][1] += av[i] * b0.y;
                acc[i][2] += av[i] * b0.z; acc[i][3] += av[i] * b0.w;
                acc[i][4] += av[i] * b1.x; acc[i][5] += av[i] * b1.y;
                acc[i][6] += av[i] * b1.z; acc[i][7] += av[i] * b1.w;
            }
        }
    }

    #pragma unroll
    for (int i = 0; i < MM; i++) {
        int m = m0 + ty * MM + i;
        float4* cp0 = (float4*)&C[(size_t)m * N + n0 + tx * 8];
        float4* cp1 = cp0 + 1;
        float4 v0, v1;
        if (EPI_ADD) {
            float4 o0 = *cp0, o1 = *cp1;
            v0 = make_float4(o0.x + acc[i][0], o0.y + acc[i][1], o0.z + acc[i][2], o0.w + acc[i][3]);
            v1 = make_float4(o1.x + acc[i][4], o1.y + acc[i][5], o1.z + acc[i][6], o1.w + acc[i][7]);
        } else {
            v0 = make_float4(acc[i][0], acc[i][1], acc[i][2], acc[i][3]);
            v1 = make_float4(acc[i][4], acc[i][5], acc[i][6], acc[i][7]);
        }
        *cp0 = v0; *cp1 = v1;
    }
}

// ------------------------- depthwise conv 3x3 + bias + silu ------------------
__global__ void conv_silu_kernel(const float* __restrict__ xz,
                                 const float* __restrict__ cw,
                                 const float* __restrict__ cb,
                                 float* __restrict__ urow, float* __restrict__ ucol) {
    int bid = blockIdx.x;               // B*L*2 = 8192 blocks
    int tid = threadIdx.x;              // 256
    int d  = ((bid & 1) << 8) + tid;
    int hw = (bid >> 1) & (LL - 1);
    int b  = bid >> 11;
    int h = hw >> 5, w = hw & 31;
    float acc = cb[d];
    const float* wt = cw + d * 9;
    const float* xb = xz + (size_t)b * LL * (2 * DI);
    #pragma unroll
    for (int i = 0; i < 3; i++) {
        int hh = h + i - 1;
        if ((unsigned)hh < (unsigned)HH) {
            #pragma unroll
            for (int jj = 0; jj < 3; jj++) {
                int ww = w + jj - 1;
                if ((unsigned)ww < (unsigned)WW)
                    acc += wt[i * 3 + jj] * xb[(size_t)(hh * WW + ww) * (2 * DI) + d];
            }
        }
    }
    float s = acc / (1.f + expf(-acc));
    urow[((size_t)b * LL + hw) * DI + d] = s;
    int posc = (w << 5) | h;
    ucol[((size_t)b * LL + posc) * DI + d] = s;
}

// ------------------------- x_proj GEMM: (48 x L) = W(48x512) @ U^T -----------
__global__ void gemm_xdbl(const float* __restrict__ xpw,
                          const float* __restrict__ urow, const float* __restrict__ ucol,
                          float* __restrict__ dts, float* __restrict__ BC) {
    __shared__ float As[16][53];
    __shared__ __align__(16) float Bs[16][68];
    int bk = blockIdx.y;
    int b = bk >> 2, k = bk & 3;
    int l0 = blockIdx.x * 64;
    const float* A = xpw + (size_t)k * 48 * DI;
    const float* U = ((k & 1) ? ucol : urow) + (size_t)b * LL * DI;
    int tid = threadIdx.x;
    int tx = tid & 15, ty = tid >> 4;
    float acc[3][4];
    #pragma unroll
    for (int i = 0; i < 3; i++)
        #pragma unroll
        for (int j = 0; j < 4; j++) acc[i][j] = 0.f;

    for (int k0 = 0; k0 < DI; k0 += 16) {
        #pragma unroll
        for (int it = 0; it < 3; it++) {
            int e = tid + it * 256;
            int c = e >> 4, kk = e & 15;
            As[kk][c] = A[(size_t)c * DI + k0 + kk];
        }
        #pragma unroll
        for (int it = 0; it < 4; it++) {
            int e = tid + it * 256;
            int l = e >> 4, kk = e & 15;
            Bs[kk][l] = U[(size_t)(l0 + l) * DI + k0 + kk];
        }
        __syncthreads();
        #pragma unroll
        for (int kk = 0; kk < 16; kk++) {
            float a0 = As[kk][ty * 3 + 0];
            float a1 = As[kk][ty * 3 + 1];
            float a2 = As[kk][ty * 3 + 2];
            float4 bv = *(const float4*)&Bs[kk][tx * 4];
            acc[0][0] += a0 * bv.x; acc[0][1] += a0 * bv.y; acc[0][2] += a0 * bv.z; acc[0][3] += a0 * bv.w;
            acc[1][0] += a1 * bv.x; acc[1][1] += a1 * bv.y; acc[1][2] += a1 * bv.z; acc[1][3] += a1 * bv.w;
            acc[2][0] += a2 * bv.x; acc[2][1] += a2 * bv.y; acc[2][2] += a2 * bv.z; acc[2][3] += a2 * bv.w;
        }
        __syncthreads();
    }
    #pragma unroll
    for (int i = 0; i < 3; i++) {
        int c = ty * 3 + i;
        #pragma unroll
        for (int j = 0; j < 4; j++) {
            int l = l0 + tx * 4 + j;
            float v = acc[i][j];
            if (c < RR) dts[((size_t)bk * RR + c) * LL + l] = v;
            else        BC[((size_t)bk * LL + l) * (2 * NS) + (c - RR)] = v;
        }
    }
}

// ------------------------- chunked selective scan ----------------------------
// PASS2=0: per-chunk local end-state (h0=0) + sum of delta.
// PASS2=1: re-run each chunk from the true start state, emit y into contrib.
// dt_proj + softplus fused (weights in regs, dts tile transposed in smem).
template <int PASS2>
__global__ __launch_bounds__(128) void scan_chunk_kernel(
        const float* __restrict__ urow, const float* __restrict__ ucol,
        const float* __restrict__ BC,
        const float* __restrict__ dts,    // (bk, r, l)
        const float* __restrict__ dtw,    // (K,512,16) layer slice
        const float* __restrict__ dtb,    // (K,512)    layer slice
        const float* __restrict__ A_log,  // (K*DI, 16) layer slice
        const float* __restrict__ Ds,     // (K*DI)     layer slice
        const float* __restrict__ hstart, // pass2 in
        float* __restrict__ hend,         // pass1 out
        float* __restrict__ Ssum,         // pass1 out
        float* __restrict__ contrib) {    // pass2 out
    __shared__ __align__(16) float s_dts[CH][20];   // [pos][r], padded
    int tid = threadIdx.x;
    int d  = blockIdx.x * 128 + tid;
    int c  = blockIdx.y;
    int bk = blockIdx.z;
    int k = bk & 3, b = bk >> 2;
    const bool rev = (k >= 2);
    int jbase = rev ? (LL - CH * (c + 1)) : CH * c;

    // stage the dts tile, transposed: s_dts[i][r]
    #pragma unroll
    for (int idx = tid; idx < RR * CH; idx += 128) {
        int r = idx >> 6, i = idx & (CH - 1);
        s_dts[i][r] = dts[((size_t)bk * RR + r) * LL + jbase + i];
    }
    __syncthreads();

    // dt_proj weights + bias
    const float4* w4 = (const float4*)(dtw + (size_t)(k * DI + d) * RR);
    float4 w0 = w4[0], w1 = w4[1], w2 = w4[2], w3 = w4[3];
    float bias = dtb[k * DI + d];

    // A row; detect A[n] == (n+1)*A[0] structure (true for this model)
    const float* arow = A_log + (size_t)(k * DI + d) * NS;
    float a0 = -expf(arow[0]);
    bool trick = true;
    #pragma unroll
    for (int n = 1; n < NS; n++) {
        float an = -expf(arow[n]);
        if (fabsf(an - (float)(n + 1) * a0) > 1e-5f * fabsf(an)) trick = false;
    }

    float h[NS];
    size_t hbase = ((size_t)(bk * NCH + c) * DI + d) * NS;
    if (PASS2) {
        const float4* hp = (const float4*)(hstart + hbase);
        #pragma unroll
        for (int q = 0; q < 4; q++) {
            float4 t = hp[q];
            h[q*4+0] = t.x; h[q*4+1] = t.y; h[q*4+2] = t.z; h[q*4+3] = t.w;
        }
    } else {
        #pragma unroll
        for (int n = 0; n < NS; n++) h[n] = 0.f;
    }
    float Dv = PASS2 ? Ds[k * DI + d] : 0.f;

    const float* u_base  = ((k & 1) ? ucol : urow) + (size_t)b * LL * DI + d;
    const float4* bc_base = (const float4*)(BC + (size_t)bk * LL * (2 * NS));
    float* out_base = PASS2 ? (contrib + (size_t)bk * LL * DI + d) : (float*)0;
    float S = 0.f;

    if (trick) {
        for (int t = 0; t < CH; t++) {
            int jl = rev ? (CH - 1 - t) : t;
            int j  = jbase + jl;
            const float4* dp = (const float4*)&s_dts[jl][0];
            float4 d0 = dp[0], d1 = dp[1], d2 = dp[2], d3 = dp[3];
            float acc = bias;
            acc += w0.x*d0.x + w0.y*d0.y + w0.z*d0.z + w0.w*d0.w;
            acc += w1.x*d1.x + w1.y*d1.y + w1.z*d1.z + w1.w*d1.w;
            acc += w2.x*d2.x + w2.y*d2.y + w2.z*d2.z + w2.w*d2.w;
            acc += w3.x*d3.x + w3.y*d3.y + w3.z*d3.z + w3.w*d3.w;
            float dv = softplus_f(acc);
            S += dv;
            float u  = u_base[(size_t)j * DI];
            float du = dv * u;
            const float4* bc = bc_base + (size_t)j * 8;
            float x = __expf(dv * a0);
            float p = x;
            float y = Dv * u;
            #pragma unroll
            for (int q = 0; q < 4; q++) {
                float4 Bq = bc[q];
                float4 Cq;
                if (PASS2) Cq = bc[q + 4];
                h[q*4+0] = p*h[q*4+0] + du*Bq.x; if (PASS2) y += h[q*4+0]*Cq.x; p *= x;
                h[q*4+1] = p*h[q*4+1] + du*Bq.y; if (PASS2) y += h[q*4+1]*Cq.y; p *= x;
                h[q*4+2] = p*h[q*4+2] + du*Bq.z; if (PASS2) y += h[q*4+2]*Cq.z; p *= x;
                h[q*4+3] = p*h[q*4+3] + du*Bq.w; if (PASS2) y += h[q*4+3]*Cq.w;
                if (q < 3) p *= x;
            }
            if (PASS2) {
                int pos = (k & 1) ? (((j & 31) << 5) | (j >> 5)) : j;
                out_base[(size_t)pos * DI] = y;
            }
        }
    } else {
        float Aexp[NS];
        #pragma unroll
        for (int n = 0; n < NS; n++) Aexp[n] = -expf(arow[n]);
        for (int t = 0; t < CH; t++) {
            int jl = rev ? (CH - 1 - t) : t;
            int j  = jbase + jl;
            const float4* dp = (const float4*)&s_dts[jl][0];
            float4 d0 = dp[0], d1 = dp[1], d2 = dp[2], d3 = dp[3];
            float acc = bias;
            acc += w0.x*d0.x + w0.y*d0.y + w0.z*d0.z + w0.w*d0.w;
            acc += w1.x*d1.x + w1.y*d1.y + w1.z*d1.z + w1.w*d1.w;
            acc += w2.x*d2.x + w2.y*d2.y + w2.z*d2.z + w2.w*d2.w;
            acc += w3.x*d3.x + w3.y*d3.y + w3.z*d3.z + w3.w*d3.w;
            float dv = softplus_f(acc);
            S += dv;
            float u  = u_base[(size_t)j * DI];
            float du = dv * u;
            const float4* bc = bc_base + (size_t)j * 8;
            float y = Dv * u;
            #pragma unroll
            for (int q = 0; q < 4; q++) {
                float4 Bq = bc[q];
                float4 Cq;
                if (PASS2) Cq = bc[q + 4];
                float dA;
                dA = __expf(dv*Aexp[q*4+0]); h[q*4+0] = dA*h[q*4+0] + du*Bq.x; if (PASS2) y += h[q*4+0]*Cq.x;
                dA = __expf(dv*Aexp[q*4+1]); h[q*4+1] = dA*h[q*4+1] + du*Bq.y; if (PASS2) y += h[q*4+1]*Cq.y;
                dA = __expf(dv*Aexp[q*4+2]); h[q*4+2] = dA*h[q*4+2] + du*Bq.z; if (PASS2) y += h[q*4+2]*Cq.z;
                dA = __expf(dv*Aexp[q*4+3]); h[q*4+3] = dA*h[q*4+3] + du*Bq.w; if (PASS2) y += h[q*4+3]*Cq.w;
            }
            if (PASS2) {
                int pos = (k & 1) ? (((j & 31) << 5) | (j >> 5)) : j;
                out_base[(size_t)pos * DI] = y;
            }
        }
    }

    if (!PASS2) {
        float4* hp = (float4*)(hend + hbase);
        #pragma unroll
        for (int q = 0; q < 4; q++)
            hp[q] = make_float4(h[q*4+0], h[q*4+1], h[q*4+2], h[q*4+3]);
        Ssum[(size_t)(bk * NCH + c) * DI + d] = S;
    }
}

// combine chunk summaries sequentially -> true start state per chunk
__global__ __launch_bounds__(128) void scan_combine_kernel(
        const float* __restrict__ hend, const float* __restrict__ Ssum,
        const float* __restrict__ A_log, float* __restrict__ hstart) {
    int cid = blockIdx.x * 128 + threadIdx.x;   // 0..8191 = bk*512+d
    int d  = cid & (DI - 1);
    int bk = cid >> 9;
    int k  = bk & 3;

    const float* arow = A_log + (size_t)(k * DI + d) * NS;
    float a0 = -expf(arow[0]);
    bool trick = true;
    #pragma unroll
    for (int n = 1; n < NS; n++) {
        float an = -expf(arow[n]);
        if (fabsf(an - (float)(n + 1) * a0) > 1e-5f * fabsf(an)) trick = false;
    }

    float h[NS];
    #pragma unroll
    for (int n = 0; n < NS; n++) h[n] = 0.f;

    for (int c = 0; c < NCH; c++) {
        size_t base = ((size_t)(bk * NCH + c) * DI + d) * NS;
        float4* hs = (float4*)(hstart + base);
        #pragma unroll
        for (int q = 0; q < 4; q++)
            hs[q] = make_float4(h[q*4+0], h[q*4+1], h[q*4+2], h[q*4+3]);

        float S = Ssum[(size_t)(bk * NCH + c) * DI + d];
        const float4* hp = (const float4*)(hend + base);
        if (trick) {
            float x = __expf(S * a0);
            float p = x;
            #pragma unroll
            for (int q = 0; q < 4; q++) {
                float4 he = hp[q];
                h[q*4+0] = p*h[q*4+0] + he.x; p *= x;
                h[q*4+1] = p*h[q*4+1] + he.y; p *= x;
                h[q*4+2] = p*h[q*4+2] + he.z; p *= x;
                h[q*4+3] = p*h[q*4+3] + he.w;
                if (q < 3) p *= x;
            }
        } else {
            #pragma unroll
            for (int q = 0; q < 4; q++) {
                float4 he = hp[q];
                h[q*4+0] = __expf(S * -expf(arow[q*4+0]))*h[q*4+0] + he.x;
                h[q*4+1] = __expf(S * -expf(arow[q*4+1]))*h[q*4+1] + he.y;
                h[q*4+2] = __expf(S * -expf(arow[q*4+2]))*h[q*4+2] + he.z;
                h[q*4+3] = __expf(S * -expf(arow[q*4+3]))*h[q*4+3] + he.w;
            }
        }
    }
}

// ------------------------- merge + out_norm + gate ---------------------------
__global__ void merge_ln_gate(const float* __restrict__ contrib,
                              const float* __restrict__ xz,
                              const float* __restrict__ onw,
                              const float* __restrict__ onb,
                              float* __restrict__ yg) {
    __shared__ float red[32];
    int row = blockIdx.x;
    int b = row >> 10;
    int l = row & (LL - 1);
    int tid = threadIdx.x;
    float v[2];
    #pragma unroll
    for (int hh = 0; hh < 2; hh++) {
        int d = tid + hh * 256;
        size_t base = ((size_t)(b * KK) * LL + l) * DI + d;
        const size_t stride = (size_t)LL * DI;
        v[hh] = contrib[base] + contrib[base + stride]
              + contrib[base + 2 * stride] + contrib[base + 3 * stride];
    }
    float sum = block_reduce_sum_256(v[0] + v[1], red, tid);
    float mean = sum * (1.f / DI);
    float d0 = v[0] - mean, d1 = v[1] - mean;
    float sq = block_reduce_sum_256(d0 * d0 + d1 * d1, red, tid);
    float rstd = rsqrtf(sq * (1.f / DI) + 1e-5f);
    #pragma unroll
    for (int hh = 0; hh < 2; hh++) {
        int d = tid + hh * 256;
        float yn = (v[hh] - mean) * rstd * onw[d] + onb[d];
        float z = xz[(size_t)row * (2 * DI) + DI + d];
        yg[(size_t)row * DI + d] = yn * (z / (1.f + expf(-z)));
    }
}

// ---------------------------------------------------------------------------
extern "C" void kernel_launch(void* const* d_in, const int* in_sizes, int n_in,
                              void* d_out, int out_size) {
    const float* x          = (const float*)d_in[0];
    const float* ln1_w      = (const float*)d_in[1];
    const float* ln1_b      = (const float*)d_in[2];
    const float* in_proj_w  = (const float*)d_in[3];
    const float* conv_w     = (const float*)d_in[4];
    const float* conv_b     = (const float*)d_in[5];
    const float* x_proj_w   = (const float*)d_in[6];
    const float* dt_proj_w  = (const float*)d_in[7];
    const float* dt_proj_b  = (const float*)d_in[8];
    const float* A_log      = (const float*)d_in[9];
    const float* Ds         = (const float*)d_in[10];
    const float* out_norm_w = (const float*)d_in[11];
    const float* out_norm_b = (const float*)d_in[12];
    const float* out_proj_w = (const float*)d_in[13];

    float *xnhwc, *xn, *xz, *urow, *ucol, *dts, *bc, *hend, *hstart, *ssum, *contrib, *yg;
    cudaGetSymbolAddress((void**)&xnhwc,   g_xnhwc);
    cudaGetSymbolAddress((void**)&xn,      g_xn);
    cudaGetSymbolAddress((void**)&xz,      g_xz);
    cudaGetSymbolAddress((void**)&urow,    g_urow);
    cudaGetSymbolAddress((void**)&ucol,    g_ucol);
    cudaGetSymbolAddress((void**)&dts,     g_dts);
    cudaGetSymbolAddress((void**)&bc,      g_BC);
    cudaGetSymbolAddress((void**)&hend,    g_hend);
    cudaGetSymbolAddress((void**)&hstart,  g_hstart);
    cudaGetSymbolAddress((void**)&ssum,    g_Ssum);
    cudaGetSymbolAddress((void**)&contrib, g_contrib);
    cudaGetSymbolAddress((void**)&yg,      g_yg);

    // NCHW -> NHWC
    transpose_k<<<dim3(LL / 32, CC / 32, BB), dim3(32, 8)>>>(xnhwc, x, CC, LL);

    for (int layer = 0; layer < NLAYER; layer++) {
        const float* l_ln1w = ln1_w      + (size_t)layer * CC;
        const float* l_ln1b = ln1_b      + (size_t)layer * CC;
        const float* l_ipw  = in_proj_w  + (size_t)layer * 2 * DI * CC;
        const float* l_cw   = conv_w     + (size_t)layer * DI * 9;
        const float* l_cb   = conv_b     + (size_t)layer * DI;
        const float* l_xpw  = x_proj_w   + (size_t)layer * KK * 48 * DI;
        const float* l_dtw  = dt_proj_w  + (size_t)layer * KK * DI * RR;
        const float* l_dtb  = dt_proj_b  + (size_t)layer * KK * DI;
        const float* l_alog = A_log      + (size_t)layer * KK * DI * NS;
        const float* l_ds   = Ds         + (size_t)layer * KK * DI;
        const float* l_onw  = out_norm_w + (size_t)layer * DI;
        const float* l_onb  = out_norm_b + (size_t)layer * DI;
        const float* l_opw  = out_proj_w + (size_t)layer * CC * DI;

        ln1_kernel<<<BB * LL, 256>>>(xnhwc, l_ln1w, l_ln1b, xn);
        gemm_big<128, 0><<<dim3((2 * DI) / 128, (BB * LL) / 128), 256>>>(
            xn, l_ipw, xz, BB * LL, 2 * DI, CC);
        conv_silu_kernel<<<BB * LL * 2, 256>>>(xz, l_cw, l_cb, urow, ucol);
        gemm_xdbl<<<dim3(LL / 64, BB * KK), 256>>>(l_xpw, urow, ucol, dts, bc);

        scan_chunk_kernel<0><<<dim3(DI / 128, NCH, BB * KK), 128>>>(
            urow, ucol, bc, dts, l_dtw, l_dtb, l_alog, l_ds,
            (const float*)0, hend, ssum, (float*)0);
        scan_combine_kernel<<<(BB * KK * DI) / 128, 128>>>(hend, ssum, l_alog, hstart);
        scan_chunk_kernel<1><<<dim3(DI / 128, NCH, BB * KK), 128>>>(
            urow, ucol, bc, dts, l_dtw, l_dtb, l_alog, l_ds,
            hstart, (float*)0, (float*)0, contrib);

        merge_ln_gate<<<BB * LL, 256>>>(contrib, xz, l_onw, l_onb, yg);
        gemm_big<64, 1><<<dim3(CC / 64, (BB * LL) / 128), 256>>>(
            yg, l_opw, xnhwc, BB * LL, CC, DI);
    }

    // NHWC -> NCHW
    transpose_k<<<dim3(CC / 32, LL / 32, BB), dim3(32, 8)>>>((float*)d_out, xnhwc, LL, CC);
}

// round 4
// speedup vs baseline: 3.1523x; 1.0295x over previous
#include <cuda_runtime.h>
#include <mma.h>
#include <math.h>

using namespace nvcuda;

// ---------------------------------------------------------------------------
// VSS stage: 2 VSS blocks. B=4, C=256, H=W=32 (L=1024), D_inner=512,
// dt_rank=16, d_state=16, K=4 directions.
// ---------------------------------------------------------------------------

#define BB   4
#define HH   32
#define WW   32
#define LL   1024            // H*W
#define CC   256             // DIM
#define DI   512             // D_INNER
#define RR   16              // DT_RANK
#define NS   16              // D_STATE
#define KK   4
#define NLAYER 2
#define NCH  16              // scan chunks
#define CH   64              // chunk length (NCH*CH == LL)

// ------------------------- scratch (static device) -------------------------
__device__ float g_xnhwc  [BB * LL * CC];        // residual stream, NHWC
__device__ float g_xn     [BB * LL * CC];        // ln1 output
__device__ float g_xz     [BB * LL * 2 * DI];    // in_proj output (xc | z)
__device__ float g_urow   [BB * LL * DI];        // conv+silu, row order, (b,l,d)
__device__ float g_ucol   [BB * LL * DI];        // conv+silu, col order, (b,l',d)
__device__ float g_dts    [BB * KK * RR * LL];   // (bk, r, l)
__device__ float g_BC     [BB * KK * LL * 2*NS]; // (bk, l, 32)  [B | C]
__device__ float g_hend   [BB * KK * NCH * DI * NS];  // chunk-local end states
__device__ float g_hstart [BB * KK * NCH * DI * NS];  // true chunk start states
__device__ float g_Ssum   [BB * KK * NCH * DI];       // per-chunk sum of delta
__device__ float g_contrib[BB * KK * LL * DI];   // (bk, pos, d)
__device__ float g_yg     [BB * LL * DI];        // gated, pre-out_proj

// ------------------------- utilities ---------------------------------------
__device__ __forceinline__ float block_reduce_sum_256(float v, float* red, int tid) {
    #pragma unroll
    for (int o = 16; o > 0; o >>= 1) v += __shfl_xor_sync(0xffffffffu, v, o);
    int warp = tid >> 5, lane = tid & 31;
    if (lane == 0) red[warp] = v;
    __syncthreads();
    if (tid == 0) {
        float s = 0.f;
        #pragma unroll
        for (int w = 0; w < 8; w++) s += red[w];
        red[0] = s;
    }
    __syncthreads();
    float r = red[0];
    __syncthreads();
    return r;
}

__device__ __forceinline__ float softplus_f(float x) {
    return (x > 20.f) ? x : log1pf(expf(x));
}

// ------------------------- transpose (batched, 32x32 tiles) -----------------
__global__ void transpose_k(float* __restrict__ dst, const float* __restrict__ src,
                            int rows, int cols) {
    __shared__ float tile[32][33];
    int b  = blockIdx.z;
    int c0 = blockIdx.x * 32;
    int r0 = blockIdx.y * 32;
    const float* s = src + (size_t)b * rows * cols;
    float*       d = dst + (size_t)b * rows * cols;
    int tx = threadIdx.x, ty = threadIdx.y;
    #pragma unroll
    for (int i = 0; i < 32; i += 8)
        tile[ty + i][tx] = s[(size_t)(r0 + ty + i) * cols + c0 + tx];
    __syncthreads();
    #pragma unroll
    for (int i = 0; i < 32; i += 8)
        d[(size_t)(c0 + ty + i) * rows + r0 + tx] = tile[tx][ty + i];
}

// ------------------------- ln1 ---------------------------------------------
__global__ void ln1_kernel(const float* __restrict__ x, const float* __restrict__ w,
                           const float* __restrict__ bia, float* __restrict__ out) {
    __shared__ float red[32];
    int row = blockIdx.x;
    int tid = threadIdx.x;
    float v = x[(size_t)row * CC + tid];
    float mean = block_reduce_sum_256(v, red, tid) * (1.f / CC);
    float xc = v - mean;
    float var = block_reduce_sum_256(xc * xc, red, tid) * (1.f / CC);
    out[(size_t)row * CC + tid] = xc * rsqrtf(var + 1e-6f) * w[tid] + bia[tid];
}

// ------------------------- TF32 tensor-core NT GEMM --------------------------
// C[m,n] (+)= sum_k A[m,k] * B[n,k].  M,N mult of 128? (M mult 128, N mult 128)
// block tile 128x128, 8 warps = 4(m) x 2(n), warp tile 32x64 (2x4 wmma 16x16x8)
#define KB 32
template <int EPI_ADD>
__global__ __launch_bounds__(256) void gemm_tf32(
        const float* __restrict__ A, const float* __restrict__ Bm,
        float* __restrict__ C, int M, int N, int Kd) {
    __shared__ __align__(16) float As[128][40];
    __shared__ __align__(16) float Bs[128][40];
    int m0 = blockIdx.y * 128, n0 = blockIdx.x * 128;
    int tid = threadIdx.x;
    int wid = tid >> 5;
    int wm = wid & 3;           // 0..3  -> m offset wm*32
    int wn = wid >> 2;          // 0..1  -> n offset wn*64

    wmma::fragment<wmma::accumulator, 16, 16, 8, float> acc[2][4];
    #pragma unroll
    for (int i = 0; i < 2; i++)
        #pragma unroll
        for (int j = 0; j < 4; j++) {
            if (EPI_ADD) {
                const float* cp = C + (size_t)(m0 + wm * 32 + i * 16) * N
                                    + n0 + wn * 64 + j * 16;
                wmma::load_matrix_sync(acc[i][j], cp, N, wmma::mem_row_major);
            } else {
                wmma::fill_fragment(acc[i][j], 0.f);
            }
        }

    for (int k0 = 0; k0 < Kd; k0 += KB) {
        #pragma unroll
        for (int it = 0; it < 4; it++) {
            int e = tid + it * 256;          // 1024 float4 slots, 128 rows x 8
            int r = e >> 3, c4 = (e & 7) * 4;
            float4 va = *(const float4*)&A[(size_t)(m0 + r) * Kd + k0 + c4];
            As[r][c4 + 0] = wmma::__float_to_tf32(va.x);
            As[r][c4 + 1] = wmma::__float_to_tf32(va.y);
            As[r][c4 + 2] = wmma::__float_to_tf32(va.z);
            As[r][c4 + 3] = wmma::__float_to_tf32(va.w);
            float4 vb = *(const float4*)&Bm[(size_t)(n0 + r) * Kd + k0 + c4];
            Bs[r][c4 + 0] = wmma::__float_to_tf32(vb.x);
            Bs[r][c4 + 1] = wmma::__float_to_tf32(vb.y);
            Bs[r][c4 + 2] = wmma::__float_to_tf32(vb.z);
            Bs[r][c4 + 3] = wmma::__float_to_tf32(vb.w);
        }
        __syncthreads();
        #pragma unroll
        for (int kk = 0; kk < KB; kk += 8) {
            wmma::fragment<wmma::matrix_a, 16, 16, 8, wmma::precision::tf32,
                           wmma::row_major> af[2];
            wmma::fragment<wmma::matrix_b, 16, 16, 8, wmma::precision::tf32,
                           wmma::col_major> bf[4];
            #pragma unroll
            for (int i = 0; i < 2; i++)
                wmma::load_matrix_sync(af[i], &As[wm * 32 + i * 16][kk], 40);
            #pragma unroll
            for (int j = 0; j < 4; j++)
                wmma::load_matrix_sync(bf[j], &Bs[wn * 64 + j * 16][kk], 40);
            #pragma unroll
            for (int i = 0; i < 2; i++)
                #pragma unroll
                for (int j = 0; j < 4; j++)
                    wmma::mma_sync(acc[i][j], af[i], bf[j], acc[i][j]);
        }
        __syncthreads();
    }

    #pragma unroll
    for (int i = 0; i < 2; i++)
        #pragma unroll
        for (int j = 0; j < 4; j++) {
            float* cp = C + (size_t)(m0 + wm * 32 + i * 16) * N
                          + n0 + wn * 64 + j * 16;
            wmma::store_matrix_sync(cp, acc[i][j], N, wmma::mem_row_major);
        }
}

// ------------------------- depthwise conv 3x3 + bias + silu ------------------
__global__ void conv_silu_kernel(const float* __restrict__ xz,
                                 const float* __restrict__ cw,
                                 const float* __restrict__ cb,
                                 float* __restrict__ urow, float* __restrict__ ucol) {
    int bid = blockIdx.x;               // B*L*2 = 8192 blocks
    int tid = threadIdx.x;              // 256
    int d  = ((bid & 1) << 8) + tid;
    int hw = (bid >> 1) & (LL - 1);
    int b  = bid >> 11;
    int h = hw >> 5, w = hw & 31;
    float acc = cb[d];
    const float* wt = cw + d * 9;
    const float* xb = xz + (size_t)b * LL * (2 * DI);
    #pragma unroll
    for (int i = 0; i < 3; i++) {
        int hh = h + i - 1;
        if ((unsigned)hh < (unsigned)HH) {
            #pragma unroll
            for (int jj = 0; jj < 3; jj++) {
                int ww = w + jj - 1;
                if ((unsigned)ww < (unsigned)WW)
                    acc += wt[i * 3 + jj] * xb[(size_t)(hh * WW + ww) * (2 * DI) + d];
            }
        }
    }
    float s = acc / (1.f + expf(-acc));
    urow[((size_t)b * LL + hw) * DI + d] = s;
    int posc = (w << 5) | h;
    ucol[((size_t)b * LL + posc) * DI + d] = s;
}

// ------------------------- x_proj GEMM: (48 x L) = W(48x512) @ U^T -----------
__global__ void gemm_xdbl(const float* __restrict__ xpw,
                          const float* __restrict__ urow, const float* __restrict__ ucol,
                          float* __restrict__ dts, float* __restrict__ BC) {
    __shared__ float As[16][53];
    __shared__ __align__(16) float Bs[16][68];
    int bk = blockIdx.y;
    int b = bk >> 2, k = bk & 3;
    int l0 = blockIdx.x * 64;
    const float* A = xpw + (size_t)k * 48 * DI;
    const float* U = ((k & 1) ? ucol : urow) + (size_t)b * LL * DI;
    int tid = threadIdx.x;
    int tx = tid & 15, ty = tid >> 4;
    float acc[3][4];
    #pragma unroll
    for (int i = 0; i < 3; i++)
        #pragma unroll
        for (int j = 0; j < 4; j++) acc[i][j] = 0.f;

    for (int k0 = 0; k0 < DI; k0 += 16) {
        #pragma unroll
        for (int it = 0; it < 3; it++) {
            int e = tid + it * 256;
            int c = e >> 4, kk = e & 15;
            As[kk][c] = A[(size_t)c * DI + k0 + kk];
        }
        #pragma unroll
        for (int it = 0; it < 4; it++) {
            int e = tid + it * 256;
            int l = e >> 4, kk = e & 15;
            Bs[kk][l] = U[(size_t)(l0 + l) * DI + k0 + kk];
        }
        __syncthreads();
        #pragma unroll
        for (int kk = 0; kk < 16; kk++) {
            float a0 = As[kk][ty * 3 + 0];
            float a1 = As[kk][ty * 3 + 1];
            float a2 = As[kk][ty * 3 + 2];
            float4 bv = *(const float4*)&Bs[kk][tx * 4];
            acc[0][0] += a0 * bv.x; acc[0][1] += a0 * bv.y; acc[0][2] += a0 * bv.z; acc[0][3] += a0 * bv.w;
            acc[1][0] += a1 * bv.x; acc[1][1] += a1 * bv.y; acc[1][2] += a1 * bv.z; acc[1][3] += a1 * bv.w;
            acc[2][0] += a2 * bv.x; acc[2][1] += a2 * bv.y; acc[2][2] += a2 * bv.z; acc[2][3] += a2 * bv.w;
        }
        __syncthreads();
    }
    #pragma unroll
    for (int i = 0; i < 3; i++) {
        int c = ty * 3 + i;
        #pragma unroll
        for (int j = 0; j < 4; j++) {
            int l = l0 + tx * 4 + j;
            float v = acc[i][j];
            if (c < RR) dts[((size_t)bk * RR + c) * LL + l] = v;
            else        BC[((size_t)bk * LL + l) * (2 * NS) + (c - RR)] = v;
        }
    }
}

// ------------------------- chunked selective scan ----------------------------
template <int PASS2>
__global__ __launch_bounds__(128) void scan_chunk_kernel(
        const float* __restrict__ urow, const float* __restrict__ ucol,
        const float* __restrict__ BC,
        const float* __restrict__ dts,    // (bk, r, l)
        const float* __restrict__ dtw,    // (K,512,16) layer slice
        const float* __restrict__ dtb,    // (K,512)    layer slice
        const float* __restrict__ A_log,  // (K*DI, 16) layer slice
        const float* __restrict__ Ds,     // (K*DI)     layer slice
        const float* __restrict__ hstart, // pass2 in
        float* __restrict__ hend,         // pass1 out
        float* __restrict__ Ssum,         // pass1 out
        float* __restrict__ contrib) {    // pass2 out
    __shared__ __align__(16) float s_dts[CH][20];   // [pos][r], padded
    int tid = threadIdx.x;
    int d  = blockIdx.x * 128 + tid;
    int c  = blockIdx.y;
    int bk = blockIdx.z;
    int k = bk & 3, b = bk >> 2;
    const bool rev = (k >= 2);
    int jbase = rev ? (LL - CH * (c + 1)) : CH * c;

    #pragma unroll
    for (int idx = tid; idx < RR * CH; idx += 128) {
        int r = idx >> 6, i = idx & (CH - 1);
        s_dts[i][r] = dts[((size_t)bk * RR + r) * LL + jbase + i];
    }
    __syncthreads();

    const float4* w4 = (const float4*)(dtw + (size_t)(k * DI + d) * RR);
    float4 w0 = w4[0], w1 = w4[1], w2 = w4[2], w3 = w4[3];
    float bias = dtb[k * DI + d];

    const float* arow = A_log + (size_t)(k * DI + d) * NS;
    float a0 = -expf(arow[0]);
    bool trick = true;
    #pragma unroll
    for (int n = 1; n < NS; n++) {
        float an = -expf(arow[n]);
        if (fabsf(an - (float)(n + 1) * a0) > 1e-5f * fabsf(an)) trick = false;
    }

    float h[NS];
    size_t hbase = ((size_t)(bk * NCH + c) * DI + d) * NS;
    if (PASS2) {
        const float4* hp = (const float4*)(hstart + hbase);
        #pragma unroll
        for (int q = 0; q < 4; q++) {
            float4 t = hp[q];
            h[q*4+0] = t.x; h[q*4+1] = t.y; h[q*4+2] = t.z; h[q*4+3] = t.w;
        }
    } else {
        #pragma unroll
        for (int n = 0; n < NS; n++) h[n] = 0.f;
    }
    float Dv = PASS2 ? Ds[k * DI + d] : 0.f;

    const float* u_base  = ((k & 1) ? ucol : urow) + (size_t)b * LL * DI + d;
    const float4* bc_base = (const float4*)(BC + (size_t)bk * LL * (2 * NS));
    float* out_base = PASS2 ? (contrib + (size_t)bk * LL * DI + d) : (float*)0;
    float S = 0.f;

    if (trick) {
        for (int t = 0; t < CH; t++) {
            int jl = rev ? (CH - 1 - t) : t;
            int j  = jbase + jl;
            const float4* dp = (const float4*)&s_dts[jl][0];
            float4 d0 = dp[0], d1 = dp[1], d2 = dp[2], d3 = dp[3];
            float acc = bias;
            acc += w0.x*d0.x + w0.y*d0.y + w0.z*d0.z + w0.w*d0.w;
            acc += w1.x*d1.x + w1.y*d1.y + w1.z*d1.z + w1.w*d1.w;
            acc += w2.x*d2.x + w2.y*d2.y + w2.z*d2.z + w2.w*d2.w;
            acc += w3.x*d3.x + w3.y*d3.y + w3.z*d3.z + w3.w*d3.w;
            float dv = softplus_f(acc);
            S += dv;
            float u  = u_base[(size_t)j * DI];
            float du = dv * u;
            const float4* bc = bc_base + (size_t)j * 8;
            float x = __expf(dv * a0);
            float p = x;
            float y = Dv * u;
            #pragma unroll
            for (int q = 0; q < 4; q++) {
                float4 Bq = bc[q];
                float4 Cq;
                if (PASS2) Cq = bc[q + 4];
                h[q*4+0] = p*h[q*4+0] + du*Bq.x; if (PASS2) y += h[q*4+0]*Cq.x; p *= x;
                h[q*4+1] = p*h[q*4+1] + du*Bq.y; if (PASS2) y += h[q*4+1]*Cq.y; p *= x;
                h[q*4+2] = p*h[q*4+2] + du*Bq.z; if (PASS2) y += h[q*4+2]*Cq.z; p *= x;
                h[q*4+3] = p*h[q*4+3] + du*Bq.w; if (PASS2) y += h[q*4+3]*Cq.w;
                if (q < 3) p *= x;
            }
            if (PASS2) {
                int pos = (k & 1) ? (((j & 31) << 5) | (j >> 5)) : j;
                out_base[(size_t)pos * DI] = y;
            }
        }
    } else {
        float Aexp[NS];
        #pragma unroll
        for (int n = 0; n < NS; n++) Aexp[n] = -expf(arow[n]);
        for (int t = 0; t < CH; t++) {
            int jl = rev ? (CH - 1 - t) : t;
            int j  = jbase + jl;
            const float4* dp = (const float4*)&s_dts[jl][0];
            float4 d0 = dp[0], d1 = dp[1], d2 = dp[2], d3 = dp[3];
            float acc = bias;
            acc += w0.x*d0.x + w0.y*d0.y + w0.z*d0.z + w0.w*d0.w;
            acc += w1.x*d1.x + w1.y*d1.y + w1.z*d1.z + w1.w*d1.w;
            acc += w2.x*d2.x + w2.y*d2.y + w2.z*d2.z + w2.w*d2.w;
            acc += w3.x*d3.x + w3.y*d3.y + w3.z*d3.z + w3.w*d3.w;
            float dv = softplus_f(acc);
            S += dv;
            float u  = u_base[(size_t)j * DI];
            float du = dv * u;
            const float4* bc = bc_base + (size_t)j * 8;
            float y = Dv * u;
            #pragma unroll
            for (int q = 0; q < 4; q++) {
                float4 Bq = bc[q];
                float4 Cq;
                if (PASS2) Cq = bc[q + 4];
                float dA;
                dA = __expf(dv*Aexp[q*4+0]); h[q*4+0] = dA*h[q*4+0] + du*Bq.x; if (PASS2) y += h[q*4+0]*Cq.x;
                dA = __expf(dv*Aexp[q*4+1]); h[q*4+1] = dA*h[q*4+1] + du*Bq.y; if (PASS2) y += h[q*4+1]*Cq.y;
                dA = __expf(dv*Aexp[q*4+2]); h[q*4+2] = dA*h[q*4+2] + du*Bq.z; if (PASS2) y += h[q*4+2]*Cq.z;
                dA = __expf(dv*Aexp[q*4+3]); h[q*4+3] = dA*h[q*4+3] + du*Bq.w; if (PASS2) y += h[q*4+3]*Cq.w;
            }
            if (PASS2) {
                int pos = (k & 1) ? (((j & 31) << 5) | (j >> 5)) : j;
                out_base[(size_t)pos * DI] = y;
            }
        }
    }

    if (!PASS2) {
        float4* hp = (float4*)(hend + hbase);
        #pragma unroll
        for (int q = 0; q < 4; q++)
            hp[q] = make_float4(h[q*4+0], h[q*4+1], h[q*4+2], h[q*4+3]);
        Ssum[(size_t)(bk * NCH + c) * DI + d] = S;
    }
}

// combine chunk summaries sequentially -> true start state per chunk
__global__ __launch_bounds__(128) void scan_combine_kernel(
        const float* __restrict__ hend, const float* __restrict__ Ssum,
        const float* __restrict__ A_log, float* __restrict__ hstart) {
    int cid = blockIdx.x * 128 + threadIdx.x;   // 0..8191 = bk*512+d
    int d  = cid & (DI - 1);
    int bk = cid >> 9;
    int k  = bk & 3;

    const float* arow = A_log + (size_t)(k * DI + d) * NS;
    float a0 = -expf(arow[0]);
    bool trick = true;
    #pragma unroll
    for (int n = 1; n < NS; n++) {
        float an = -expf(arow[n]);
        if (fabsf(an - (float)(n + 1) * a0) > 1e-5f * fabsf(an)) trick = false;
    }

    float h[NS];
    #pragma unroll
    for (int n = 0; n < NS; n++) h[n] = 0.f;

    for (int c = 0; c < NCH; c++) {
        size_t base = ((size_t)(bk * NCH + c) * DI + d) * NS;
        float4* hs = (float4*)(hstart + base);
        #pragma unroll
        for (int q = 0; q < 4; q++)
            hs[q] = make_float4(h[q*4+0], h[q*4+1], h[q*4+2], h[q*4+3]);

        float S = Ssum[(size_t)(bk * NCH + c) * DI + d];
        const float4* hp = (const float4*)(hend + base);
        if (trick) {
            float x = __expf(S * a0);
            float p = x;
            #pragma unroll
            for (int q = 0; q < 4; q++) {
                float4 he = hp[q];
                h[q*4+0] = p*h[q*4+0] + he.x; p *= x;
                h[q*4+1] = p*h[q*4+1] + he.y; p *= x;
                h[q*4+2] = p*h[q*4+2] + he.z; p *= x;
                h[q*4+3] = p*h[q*4+3] + he.w;
                if (q < 3) p *= x;
            }
        } else {
            #pragma unroll
            for (int q = 0; q < 4; q++) {
                float4 he = hp[q];
                h[q*4+0] = __expf(S * -expf(arow[q*4+0]))*h[q*4+0] + he.x;
                h[q*4+1] = __expf(S * -expf(arow[q*4+1]))*h[q*4+1] + he.y;
                h[q*4+2] = __expf(S * -expf(arow[q*4+2]))*h[q*4+2] + he.z;
                h[q*4+3] = __expf(S * -expf(arow[q*4+3]))*h[q*4+3] + he.w;
            }
        }
    }
}

// ------------------------- merge + out_norm + gate ---------------------------
__global__ void merge_ln_gate(const float* __restrict__ contrib,
                              const float* __restrict__ xz,
                              const float* __restrict__ onw,
                              const float* __restrict__ onb,
                              float* __restrict__ yg) {
    __shared__ float red[32];
    int row = blockIdx.x;
    int b = row >> 10;
    int l = row & (LL - 1);
    int tid = threadIdx.x;
    float v[2];
    #pragma unroll
    for (int hh = 0; hh < 2; hh++) {
        int d = tid + hh * 256;
        size_t base = ((size_t)(b * KK) * LL + l) * DI + d;
        const size_t stride = (size_t)LL * DI;
        v[hh] = contrib[base] + contrib[base + stride]
              + contrib[base + 2 * stride] + contrib[base + 3 * stride];
    }
    float sum = block_reduce_sum_256(v[0] + v[1], red, tid);
    float mean = sum * (1.f / DI);
    float d0 = v[0] - mean, d1 = v[1] - mean;
    float sq = block_reduce_sum_256(d0 * d0 + d1 * d1, red, tid);
    float rstd = rsqrtf(sq * (1.f / DI) + 1e-5f);
    #pragma unroll
    for (int hh = 0; hh < 2; hh++) {
        int d = tid + hh * 256;
        float yn = (v[hh] - mean) * rstd * onw[d] + onb[d];
        float z = xz[(size_t)row * (2 * DI) + DI + d];
        yg[(size_t)row * DI + d] = yn * (z / (1.f + expf(-z)));
    }
}

// ---------------------------------------------------------------------------
extern "C" void kernel_launch(void* const* d_in, const int* in_sizes, int n_in,
                              void* d_out, int out_size) {
    const float* x          = (const float*)d_in[0];
    const float* ln1_w      = (const float*)d_in[1];
    const float* ln1_b      = (const float*)d_in[2];
    const float* in_proj_w  = (const float*)d_in[3];
    const float* conv_w     = (const float*)d_in[4];
    const float* conv_b     = (const float*)d_in[5];
    const float* x_proj_w   = (const float*)d_in[6];
    const float* dt_proj_w  = (const float*)d_in[7];
    const float* dt_proj_b  = (const float*)d_in[8];
    const float* A_log      = (const float*)d_in[9];
    const float* Ds         = (const float*)d_in[10];
    const float* out_norm_w = (const float*)d_in[11];
    const float* out_norm_b = (const float*)d_in[12];
    const float* out_proj_w = (const float*)d_in[13];

    float *xnhwc, *xn, *xz, *urow, *ucol, *dts, *bc, *hend, *hstart, *ssum, *contrib, *yg;
    cudaGetSymbolAddress((void**)&xnhwc,   g_xnhwc);
    cudaGetSymbolAddress((void**)&xn,      g_xn);
    cudaGetSymbolAddress((void**)&xz,      g_xz);
    cudaGetSymbolAddress((void**)&urow,    g_urow);
    cudaGetSymbolAddress((void**)&ucol,    g_ucol);
    cudaGetSymbolAddress((void**)&dts,     g_dts);
    cudaGetSymbolAddress((void**)&bc,      g_BC);
    cudaGetSymbolAddress((void**)&hend,    g_hend);
    cudaGetSymbolAddress((void**)&hstart,  g_hstart);
    cudaGetSymbolAddress((void**)&ssum,    g_Ssum);
    cudaGetSymbolAddress((void**)&contrib, g_contrib);
    cudaGetSymbolAddress((void**)&yg,      g_yg);

    // NCHW -> NHWC
    transpose_k<<<dim3(LL / 32, CC / 32, BB), dim3(32, 8)>>>(xnhwc, x, CC, LL);

    for (int layer = 0; layer < NLAYER; layer++) {
        const float* l_ln1w = ln1_w      + (size_t)layer * CC;
        const float* l_ln1b = ln1_b      + (size_t)layer * CC;
        const float* l_ipw  = in_proj_w  + (size_t)layer * 2 * DI * CC;
        const float* l_cw   = conv_w     + (size_t)layer * DI * 9;
        const float* l_cb   = conv_b     + (size_t)layer * DI;
        const float* l_xpw  = x_proj_w   + (size_t)layer * KK * 48 * DI;
        const float* l_dtw  = dt_proj_w  + (size_t)layer * KK * DI * RR;
        const float* l_dtb  = dt_proj_b  + (size_t)layer * KK * DI;
        const float* l_alog = A_log      + (size_t)layer * KK * DI * NS;
        const float* l_ds   = Ds         + (size_t)layer * KK * DI;
        const float* l_onw  = out_norm_w + (size_t)layer * DI;
        const float* l_onb  = out_norm_b + (size_t)layer * DI;
        const float* l_opw  = out_proj_w + (size_t)layer * CC * DI;

        ln1_kernel<<<BB * LL, 256>>>(xnhwc, l_ln1w, l_ln1b, xn);
        gemm_tf32<0><<<dim3((2 * DI) / 128, (BB * LL) / 128), 256>>>(
            xn, l_ipw, xz, BB * LL, 2 * DI, CC);
        conv_silu_kernel<<<BB * LL * 2, 256>>>(xz, l_cw, l_cb, urow, ucol);
        gemm_xdbl<<<dim3(LL / 64, BB * KK), 256>>>(l_xpw, urow, ucol, dts, bc);

        scan_chunk_kernel<0><<<dim3(DI / 128, NCH, BB * KK), 128>>>(
            urow, ucol, bc, dts, l_dtw, l_dtb, l_alog, l_ds,
            (const float*)0, hend, ssum, (float*)0);
        scan_combine_kernel<<<(BB * KK * DI) / 128, 128>>>(hend, ssum, l_alog, hstart);
        scan_chunk_kernel<1><<<dim3(DI / 128, NCH, BB * KK), 128>>>(
            urow, ucol, bc, dts, l_dtw, l_dtb, l_alog, l_ds,
            hstart, (float*)0, (float*)0, contrib);

        merge_ln_gate<<<BB * LL, 256>>>(contrib, xz, l_onw, l_onb, yg);
        gemm_tf32<1><<<dim3(CC / 128, (BB * LL) / 128), 256>>>(
            yg, l_opw, xnhwc, BB * LL, CC, DI);
    }

    // NHWC -> NCHW
    transpose_k<<<dim3(CC / 32, LL / 32, BB), dim3(32, 8)>>>((float*)d_out, xnhwc, LL, CC);
}